// round 12
// baseline (speedup 1.0000x reference)
#include <cuda_runtime.h>
#include <cuda_bf16.h>
#include <math.h>

#define BB 64
#define LL 512
#define HH 768
#define NN 50
#define OO 768
#define MTOT (BB*NN)   // 3200

// ---------------- scratch (device globals; no allocations allowed) ----------
__device__ float g_X[MTOT*HH];
__device__ float g_Hres[MTOT*HH];
__device__ float g_T[MTOT*HH];
__device__ float g_sp1[12*MTOT];   // partial a_src sums (per bn x warp_n)
__device__ float g_sp2[12*MTOT];   // partial a_dst sums
__device__ __nv_bfloat16 g_Ah[MTOT*HH];    // GEMM A input splits
__device__ __nv_bfloat16 g_Al[MTOT*HH];
__device__ __nv_bfloat16 g_Whh[MTOT*HH];   // Wh output splits (for mma apply)
__device__ __nv_bfloat16 g_Whl[MTOT*HH];
__device__ __nv_bfloat16 g_Bh[3*HH*HH];    // W1,W2,Wa hi
__device__ __nv_bfloat16 g_Bl[3*HH*HH];    // W1,W2,Wa lo
__device__ __nv_bfloat16 g_AttH[BB*64*64]; // padded softmax att (hi)
__device__ __nv_bfloat16 g_AttL[BB*64*64]; // padded softmax att (lo)

__device__ __forceinline__ void split1(float v, __nv_bfloat16& h, __nv_bfloat16& l) {
    h = __float2bfloat16(v);
    l = __float2bfloat16(v - __bfloat162float(h));
}

#define CP16(dst, src) \
    asm volatile("cp.async.cg.shared.global [%0], [%1], 16;\n" :: "r"(dst), "l"(src))

__device__ __forceinline__ void ldsm4(unsigned* r, const void* p) {
    unsigned addr = (unsigned)__cvta_generic_to_shared(p);
    asm volatile("ldmatrix.sync.aligned.m8n8.x4.shared.b16 {%0,%1,%2,%3}, [%4];\n"
                 : "=r"(r[0]), "=r"(r[1]), "=r"(r[2]), "=r"(r[3]) : "r"(addr));
}
__device__ __forceinline__ void ldsm4t(unsigned* r, const void* p) {
    unsigned addr = (unsigned)__cvta_generic_to_shared(p);
    asm volatile("ldmatrix.sync.aligned.m8n8.x4.trans.shared.b16 {%0,%1,%2,%3}, [%4];\n"
                 : "=r"(r[0]), "=r"(r[1]), "=r"(r[2]), "=r"(r[3]) : "r"(addr));
}
__device__ __forceinline__ void mma16816(float* c, const unsigned* a, const unsigned* b) {
    asm volatile("mma.sync.aligned.m16n8k16.row.col.f32.bf16.bf16.f32 "
                 "{%0,%1,%2,%3}, {%4,%5,%6,%7}, {%8,%9}, {%0,%1,%2,%3};\n"
                 : "+f"(c[0]), "+f"(c[1]), "+f"(c[2]), "+f"(c[3])
                 : "r"(a[0]), "r"(a[1]), "r"(a[2]), "r"(a[3]),
                   "r"(b[0]), "r"(b[1]));
}

// ---------------- 0) split the 3 mma weight matrices -----------------------
__global__ void split_weights_kernel(const float* __restrict__ w0,
                                     const float* __restrict__ w1,
                                     const float* __restrict__ w2)
{
    const float* srcs[3] = {w0, w1, w2};
    int m = blockIdx.y;
    int i = blockIdx.x * blockDim.x + threadIdx.x;
    const int n4 = HH * HH / 4;
    if (i >= n4) return;
    float4 v = ((const float4*)srcs[m])[i];
    __nv_bfloat16 h0,h1,h2,h3,l0,l1,l2,l3;
    split1(v.x,h0,l0); split1(v.y,h1,l1); split1(v.z,h2,l2); split1(v.w,h3,l3);
    __nv_bfloat162* H = (__nv_bfloat162*)(g_Bh + (size_t)m * HH * HH);
    __nv_bfloat162* L = (__nv_bfloat162*)(g_Bl + (size_t)m * HH * HH);
    H[2*i]   = __nv_bfloat162(h0,h1);
    H[2*i+1] = __nv_bfloat162(h2,h3);
    L[2*i]   = __nv_bfloat162(l0,l1);
    L[2*i+1] = __nv_bfloat162(l2,l3);
}

// ---------------- 1) gather + sinusoidal PE (+ bf16 split of X) ------------
__global__ void gather_pe_kernel(const float* __restrict__ emb,
                                 const int* __restrict__ ids)
{
    int bn = blockIdx.x;
    int b = bn / NN, n = bn % NN;
    int h = threadIdx.x * 4;
    int id = ids[bn];
    float4 e = *(const float4*)(emb + ((size_t)b * LL + id) * HH + h);
    const float c = -logf(10000.0f) / (float)HH;
    float d0 = expf((float)h * c);
    float d1 = expf((float)(h + 2) * c);
    float a0 = (float)n * d0, a1 = (float)n * d1;
    e.x += sinf(a0); e.y += cosf(a0);
    e.z += sinf(a1); e.w += cosf(a1);
    size_t off = (size_t)bn * HH + h;
    *(float4*)(g_X + off) = e;
    __nv_bfloat16 h0,h1,h2,h3,l0,l1,l2,l3;
    split1(e.x,h0,l0); split1(e.y,h1,l1); split1(e.z,h2,l2); split1(e.w,h3,l3);
    *(__nv_bfloat162*)(g_Ah + off)     = __nv_bfloat162(h0,h1);
    *(__nv_bfloat162*)(g_Ah + off + 2) = __nv_bfloat162(h2,h3);
    *(__nv_bfloat162*)(g_Al + off)     = __nv_bfloat162(l0,l1);
    *(__nv_bfloat162*)(g_Al + off + 2) = __nv_bfloat162(l2,l3);
}

// ---------------- tensor-core GEMM (bf16x3 split, fp32 accum) --------------
// KC=32, 2-stage cp.async, 2 CTAs/SM (proven R8 config).
#define KC 32
#define SA_ELEMS (2*128*40)
#define SB_ELEMS (2*32*136)
#define STAGE_ELEMS (SA_ELEMS + SB_ELEMS)   // 18944
#define SA_IDX(st,sp,r,c) ((size_t)(st)*STAGE_ELEMS + ((sp)*128 + (r))*40 + (c))
#define SB_IDX(st,sp,r,c) ((size_t)(st)*STAGE_ELEMS + SA_ELEMS + ((sp)*32 + (r))*136 + (c))
#define SMEM_BYTES (2 * STAGE_ELEMS * 2)    // 75776 B -> 2 CTAs/SM

__global__ __launch_bounds__(256, 2) void gemm_bf16x3(
    const __nv_bfloat16* __restrict__ Ah, const __nv_bfloat16* __restrict__ Al,
    const __nv_bfloat16* __restrict__ Bh, const __nv_bfloat16* __restrict__ Bl,
    const float* __restrict__ bias, float* __restrict__ C, int M,
    const float* __restrict__ avec,
    __nv_bfloat16* __restrict__ Ch, __nv_bfloat16* __restrict__ Cl)
{
    extern __shared__ __nv_bfloat16 sm[];
    const int tid = threadIdx.x;
    const int lane = tid & 31, wid = tid >> 5;
    const int warp_m = wid >> 1, warp_n = wid & 1;
    const int bm = blockIdx.y * 128, bn = blockIdx.x * 128;

    const int ar = tid >> 2, ac = (tid & 3) * 8;
    const int br = tid >> 4, bc = (tid & 15) * 8;
    const int rA0 = min(bm + ar, M - 1);
    const int rA1 = min(bm + ar + 64, M - 1);

    float acc[2][8][4] = {};
    const __nv_bfloat16* As[2] = {Ah, Al};
    const __nv_bfloat16* Bs[2] = {Bh, Bl};

    auto load_stage = [&](int st, int k0) {
        #pragma unroll
        for (int s = 0; s < 2; s++) {
            unsigned d0 = (unsigned)__cvta_generic_to_shared(&sm[SA_IDX(st, s, ar, ac)]);
            CP16(d0, As[s] + (size_t)rA0 * HH + k0 + ac);
            unsigned d1 = (unsigned)__cvta_generic_to_shared(&sm[SA_IDX(st, s, ar + 64, ac)]);
            CP16(d1, As[s] + (size_t)rA1 * HH + k0 + ac);
            unsigned e0 = (unsigned)__cvta_generic_to_shared(&sm[SB_IDX(st, s, br, bc)]);
            CP16(e0, Bs[s] + (size_t)(k0 + br) * HH + bn + bc);
            unsigned e1 = (unsigned)__cvta_generic_to_shared(&sm[SB_IDX(st, s, br + 16, bc)]);
            CP16(e1, Bs[s] + (size_t)(k0 + br + 16) * HH + bn + bc);
        }
        asm volatile("cp.async.commit_group;" ::: "memory");
    };

    load_stage(0, 0);

    const int lrow = lane & 15, lcol = (lane >> 4) * 8;
    const int NCH = HH / KC;   // 24

    for (int c = 0; c < NCH; c++) {
        asm volatile("cp.async.wait_group 0;" ::: "memory");
        __syncthreads();
        if (c + 1 < NCH) load_stage((c + 1) & 1, (c + 1) * KC);
        const int st = c & 1;

        #pragma unroll
        for (int ks = 0; ks < 2; ks++) {
            const int kb = ks * 16;
            unsigned a[2][2][4];
            #pragma unroll
            for (int mt = 0; mt < 2; mt++)
                #pragma unroll
                for (int s = 0; s < 2; s++)
                    ldsm4(a[s][mt], &sm[SA_IDX(st, s, warp_m * 32 + mt * 16 + lrow, kb + lcol)]);
            #pragma unroll
            for (int g = 0; g < 4; g++) {
                unsigned bh[4], bl[4];
                ldsm4t(bh, &sm[SB_IDX(st, 0, kb + lrow, warp_n * 64 + g * 16 + lcol)]);
                ldsm4t(bl, &sm[SB_IDX(st, 1, kb + lrow, warp_n * 64 + g * 16 + lcol)]);
                #pragma unroll
                for (int mt = 0; mt < 2; mt++) {
                    mma16816(acc[mt][2*g],   a[0][mt], bh);
                    mma16816(acc[mt][2*g],   a[0][mt], bl);
                    mma16816(acc[mt][2*g],   a[1][mt], bh);
                    mma16816(acc[mt][2*g+1], a[0][mt], bh + 2);
                    mma16816(acc[mt][2*g+1], a[0][mt], bl + 2);
                    mma16816(acc[mt][2*g+1], a[1][mt], bh + 2);
                }
            }
        }
    }

    // ---- epilogue ----
    const int er = bm + warp_m * 32 + (lane >> 2);
    const int ec = bn + warp_n * 64 + (lane & 3) * 2;
    float p1[2][2] = {}, p2[2][2] = {};
    #pragma unroll
    for (int mt = 0; mt < 2; mt++)
        #pragma unroll
        for (int nt = 0; nt < 8; nt++) {
            int r = er + mt * 16;
            int cc = ec + nt * 8;
            float b0 = bias[cc], b1 = bias[cc + 1];
            float v00 = acc[mt][nt][0] + b0, v01 = acc[mt][nt][1] + b1;
            float v10 = acc[mt][nt][2] + b0, v11 = acc[mt][nt][3] + b1;
            if (r < M) {
                size_t off = (size_t)r * HH + cc;
                if (C) { C[off] = v00; C[off + 1] = v01; }
                if (Ch) {
                    __nv_bfloat16 h0,l0,h1,l1;
                    split1(v00,h0,l0); split1(v01,h1,l1);
                    *(__nv_bfloat162*)(Ch + off) = __nv_bfloat162(h0,h1);
                    *(__nv_bfloat162*)(Cl + off) = __nv_bfloat162(l0,l1);
                }
            }
            if (r + 8 < M) {
                size_t off = (size_t)(r + 8) * HH + cc;
                if (C) { C[off] = v10; C[off + 1] = v11; }
                if (Ch) {
                    __nv_bfloat16 h0,l0,h1,l1;
                    split1(v10,h0,l0); split1(v11,h1,l1);
                    *(__nv_bfloat162*)(Ch + off) = __nv_bfloat162(h0,h1);
                    *(__nv_bfloat162*)(Cl + off) = __nv_bfloat162(l0,l1);
                }
            }
            if (avec) {
                float au0 = avec[cc], au1 = avec[cc + 1];
                float av0 = avec[HH + cc], av1 = avec[HH + cc + 1];
                p1[mt][0] += v00 * au0 + v01 * au1;
                p2[mt][0] += v00 * av0 + v01 * av1;
                p1[mt][1] += v10 * au0 + v11 * au1;
                p2[mt][1] += v10 * av0 + v11 * av1;
            }
        }
    if (avec) {
        #pragma unroll
        for (int mt = 0; mt < 2; mt++)
            #pragma unroll
            for (int h = 0; h < 2; h++) {
                #pragma unroll
                for (int o = 1; o <= 2; o <<= 1) {
                    p1[mt][h] += __shfl_xor_sync(~0u, p1[mt][h], o);
                    p2[mt][h] += __shfl_xor_sync(~0u, p2[mt][h], o);
                }
            }
        if ((lane & 3) == 0) {
            int slot = blockIdx.x * 2 + warp_n;
            #pragma unroll
            for (int mt = 0; mt < 2; mt++)
                #pragma unroll
                for (int h = 0; h < 2; h++) {
                    int r = er + mt * 16 + h * 8;
                    if (r < M) {
                        g_sp1[(size_t)slot * MTOT + r] = p1[mt][h];
                        g_sp2[(size_t)slot * MTOT + r] = p2[mt][h];
                    }
                }
        }
    }
}

// -- 3a) softmax: reduce partials + masked softmax -> padded bf16 att ------
__global__ __launch_bounds__(256) void softmax_kernel(
    const int* __restrict__ adj, const float* __restrict__ ab)
{
    int b = blockIdx.x;
    int t = threadIdx.x, lane = t & 31, w = t >> 5;
    __shared__ float asrc_s[NN], adst_s[NN];
    if (t < 2 * NN) {
        int i = t % NN;
        const float* sp = (t < NN) ? g_sp1 : g_sp2;
        float s = 0.f;
        #pragma unroll
        for (int c = 0; c < 12; c++) s += sp[(size_t)c * MTOT + b * NN + i];
        ((t < NN) ? asrc_s : adst_s)[i] = s;
    }
    __syncthreads();

    float abv = *ab;
    __nv_bfloat16* attH = g_AttH + (size_t)b * 64 * 64;
    __nv_bfloat16* attL = g_AttL + (size_t)b * 64 * 64;
    for (int i = w; i < 64; i += 8) {
        int j2 = lane + 32;
        if (i < NN) {
            float ai = asrc_s[i];
            const int* adjr = adj + ((size_t)b * NN + i) * NN;
            float v0 = ai + adst_s[lane] + abv;
            v0 = v0 >= 0.f ? v0 : 0.3f * v0;
            float e0 = (adjr[lane] > 0) ? v0 : -1e30f;
            float e1 = -1e30f;
            if (j2 < NN) {
                float v1 = ai + adst_s[j2] + abv;
                v1 = v1 >= 0.f ? v1 : 0.3f * v1;
                e1 = (adjr[j2] > 0) ? v1 : -1e30f;
            }
            float m = fmaxf(e0, e1);
            #pragma unroll
            for (int o = 16; o; o >>= 1) m = fmaxf(m, __shfl_xor_sync(~0u, m, o));
            float x0 = expf(e0 - m);
            float x1 = (j2 < NN) ? expf(e1 - m) : 0.f;
            float s = x0 + x1;
            #pragma unroll
            for (int o = 16; o; o >>= 1) s += __shfl_xor_sync(~0u, s, o);
            float inv = 1.f / s;
            split1(x0 * inv, attH[i * 64 + lane], attL[i * 64 + lane]);
            if (j2 < NN) split1(x1 * inv, attH[i * 64 + j2], attL[i * 64 + j2]);
            else { attH[i * 64 + j2] = __nv_bfloat16(0.f); attL[i * 64 + j2] = __nv_bfloat16(0.f); }
        } else {
            attH[i * 64 + lane] = __nv_bfloat16(0.f); attL[i * 64 + lane] = __nv_bfloat16(0.f);
            attH[i * 64 + j2]   = __nv_bfloat16(0.f); attL[i * 64 + j2]   = __nv_bfloat16(0.f);
        }
    }
}

// -- 3b) apply: pure bf16x3 mma (att @ Wh), elu, residual, split outputs ----
#define AP_ATT_H 0
#define AP_ATT_L 4608
#define AP_WH_H  9216
#define AP_WH_L  17920
#define AP_SMEM_BYTES (26624*2 + 256)   // 53504

__global__ __launch_bounds__(256, 2) void gat_apply_kernel(
    const __nv_bfloat16* __restrict__ Whh, const __nv_bfloat16* __restrict__ Whl,
    const float* __restrict__ resid, float* __restrict__ out_f32,
    __nv_bfloat16* __restrict__ hi, __nv_bfloat16* __restrict__ lo)
{
    extern __shared__ __nv_bfloat16 sm2[];
    int b = blockIdx.y, ch = blockIdx.x;
    int t = threadIdx.x, lane = t & 31, w = t >> 5;

    // async loads: att (padded 64x64 hi/lo) + Wh chunk (64x128 hi/lo)
    {
        const __nv_bfloat16* aH = g_AttH + (size_t)b * 64 * 64;
        const __nv_bfloat16* aL = g_AttL + (size_t)b * 64 * 64;
        #pragma unroll
        for (int p = 0; p < 2; p++) {
            int row = (t >> 3) + p * 32;
            int cg = (t & 7) * 8;
            unsigned dh = (unsigned)__cvta_generic_to_shared(&sm2[AP_ATT_H + row * 72 + cg]);
            CP16(dh, aH + row * 64 + cg);
            unsigned dl = (unsigned)__cvta_generic_to_shared(&sm2[AP_ATT_L + row * 72 + cg]);
            CP16(dl, aL + row * 64 + cg);
        }
        int kr = t >> 2;
        int cg = (t & 3) * 8;
        int grow = b * NN + min(kr, NN - 1);   // rows >= NN: att coeff is zero
        const __nv_bfloat16* srch = Whh + (size_t)grow * HH + ch * 128;
        const __nv_bfloat16* srcl = Whl + (size_t)grow * HH + ch * 128;
        #pragma unroll
        for (int p = 0; p < 4; p++) {
            int col = cg + p * 32;
            unsigned dh = (unsigned)__cvta_generic_to_shared(&sm2[AP_WH_H + kr * 136 + col]);
            CP16(dh, srch + col);
            unsigned dl = (unsigned)__cvta_generic_to_shared(&sm2[AP_WH_L + kr * 136 + col]);
            CP16(dl, srcl + col);
        }
        asm volatile("cp.async.commit_group;\n" ::: "memory");
        asm volatile("cp.async.wait_group 0;\n" ::: "memory");
    }
    __syncthreads();

    const int lrow = lane & 15, lcol = (lane >> 4) * 8;
    const int n0 = w * 16;
    float acc[4][2][4] = {};
    #pragma unroll
    for (int kb = 0; kb < 64; kb += 16) {
        unsigned ah[4][4], al[4][4];
        #pragma unroll
        for (int mt = 0; mt < 4; mt++) {
            ldsm4(ah[mt], &sm2[AP_ATT_H + (mt * 16 + lrow) * 72 + kb + lcol]);
            ldsm4(al[mt], &sm2[AP_ATT_L + (mt * 16 + lrow) * 72 + kb + lcol]);
        }
        unsigned bh[4], bl[4];
        ldsm4t(bh, &sm2[AP_WH_H + (kb + lrow) * 136 + n0 + lcol]);
        ldsm4t(bl, &sm2[AP_WH_L + (kb + lrow) * 136 + n0 + lcol]);
        #pragma unroll
        for (int mt = 0; mt < 4; mt++) {
            mma16816(acc[mt][0], ah[mt], bh);
            mma16816(acc[mt][0], ah[mt], bl);
            mma16816(acc[mt][0], al[mt], bh);
            mma16816(acc[mt][1], ah[mt], bh + 2);
            mma16816(acc[mt][1], ah[mt], bl + 2);
            mma16816(acc[mt][1], al[mt], bh + 2);
        }
    }
    #pragma unroll
    for (int mt = 0; mt < 4; mt++)
        #pragma unroll
        for (int nt = 0; nt < 2; nt++) {
            int cc = ch * 128 + n0 + nt * 8 + (lane & 3) * 2;
            #pragma unroll
            for (int h = 0; h < 2; h++) {
                int row = mt * 16 + (lane >> 2) + h * 8;
                if (row < NN) {
                    float vx = acc[mt][nt][2*h], vy = acc[mt][nt][2*h + 1];
                    vx = vx > 0.f ? vx : expm1f(vx);
                    vy = vy > 0.f ? vy : expm1f(vy);
                    size_t off = ((size_t)b * NN + row) * HH + cc;
                    if (resid) { vx += resid[off]; vy += resid[off + 1]; }
                    if (out_f32) { out_f32[off] = vx; out_f32[off + 1] = vy; }
                    __nv_bfloat16 h0,l0,h1,l1;
                    split1(vx,h0,l0); split1(vy,h1,l1);
                    *(__nv_bfloat162*)(hi + off) = __nv_bfloat162(h0,h1);
                    *(__nv_bfloat162*)(lo + off) = __nv_bfloat162(l0,l1);
                }
            }
        }
}

// -------- 5+6) fused: attention pooling -> D (smem) -> out = D @ Wl + bl ---
__global__ __launch_bounds__(256) void pool_final_kernel(
    const float* __restrict__ T, const float* __restrict__ v,
    const float* __restrict__ Hres, const float* __restrict__ W,
    const float* __restrict__ bias, float* __restrict__ out)
{
    int b = blockIdx.x;
    int t = threadIdx.x, lane = t & 31, w = t >> 5;
    __shared__ float sc[NN];
    __shared__ float Ds[HH];
    for (int n = w; n < NN; n += 8) {
        const float4* row = (const float4*)(T + ((size_t)b * NN + n) * HH);
        float s = 0.f;
        for (int c2 = lane; c2 < HH / 4; c2 += 32) {
            float4 x = row[c2];
            float4 u = ((const float4*)v)[c2];
            s += tanhf(x.x) * u.x + tanhf(x.y) * u.y +
                 tanhf(x.z) * u.z + tanhf(x.w) * u.w;
        }
        #pragma unroll
        for (int o = 16; o; o >>= 1) s += __shfl_xor_sync(~0u, s, o);
        if (lane == 0) sc[n] = s;
    }
    __syncthreads();
    if (t == 0) {
        float m = -1e30f;
        for (int n = 0; n < NN; n++) m = fmaxf(m, sc[n]);
        float s = 0.f;
        for (int n = 0; n < NN; n++) { sc[n] = expf(sc[n] - m); s += sc[n]; }
        float inv = 1.f / s;
        for (int n = 0; n < NN; n++) sc[n] *= inv;
    }
    __syncthreads();
    for (int h = t; h < HH; h += 256) {
        float acc = 0.f;
        #pragma unroll 5
        for (int n = 0; n < NN; n++)
            acc = fmaf(sc[n], Hres[((size_t)b * NN + n) * HH + h], acc);
        Ds[h] = acc;
    }
    __syncthreads();
    #pragma unroll
    for (int oc = 0; oc < 3; oc++) {
        int o = t + oc * 256;
        float acc = 0.f;
        #pragma unroll 8
        for (int h = 0; h < HH; h++)
            acc = fmaf(Ds[h], W[(size_t)h * OO + o], acc);
        out[(size_t)b * OO + o] = acc + bias[o];
    }
}

// ---------------- launch ----------------------------------------------------
extern "C" void kernel_launch(void* const* d_in, const int* in_sizes, int n_in,
                              void* d_out, int out_size)
{
    const float* emb = (const float*)d_in[0];
    const int*   ids = (const int*)  d_in[1];
    const int*   adj = (const int*)  d_in[2];
    const float* W1  = (const float*)d_in[3];
    const float* b1  = (const float*)d_in[4];
    const float* a1  = (const float*)d_in[5];
    const float* ab1 = (const float*)d_in[6];
    const float* W2  = (const float*)d_in[7];
    const float* b2  = (const float*)d_in[8];
    const float* a2  = (const float*)d_in[9];
    const float* ab2 = (const float*)d_in[10];
    const float* Wa  = (const float*)d_in[11];
    const float* ba  = (const float*)d_in[12];
    const float* v   = (const float*)d_in[13];
    const float* Wl  = (const float*)d_in[14];
    const float* bl  = (const float*)d_in[15];
    float* out = (float*)d_out;

    void *pX, *pHres, *pT, *pAh, *pAl, *pWhh, *pWhl, *pBh, *pBl;
    cudaGetSymbolAddress(&pX, g_X);
    cudaGetSymbolAddress(&pHres, g_Hres);
    cudaGetSymbolAddress(&pT, g_T);
    cudaGetSymbolAddress(&pAh, g_Ah);
    cudaGetSymbolAddress(&pAl, g_Al);
    cudaGetSymbolAddress(&pWhh, g_Whh);
    cudaGetSymbolAddress(&pWhl, g_Whl);
    cudaGetSymbolAddress(&pBh, g_Bh);
    cudaGetSymbolAddress(&pBl, g_Bl);
    float* X    = (float*)pX;
    float* Hres = (float*)pHres;
    float* T    = (float*)pT;
    __nv_bfloat16* Ah  = (__nv_bfloat16*)pAh;
    __nv_bfloat16* Al  = (__nv_bfloat16*)pAl;
    __nv_bfloat16* Whh = (__nv_bfloat16*)pWhh;
    __nv_bfloat16* Whl = (__nv_bfloat16*)pWhl;
    __nv_bfloat16* Bh  = (__nv_bfloat16*)pBh;
    __nv_bfloat16* Bl  = (__nv_bfloat16*)pBl;
    const size_t WSZ = (size_t)HH * HH;

    cudaFuncSetAttribute(gemm_bf16x3,
                         cudaFuncAttributeMaxDynamicSharedMemorySize, SMEM_BYTES);
    cudaFuncSetAttribute(gat_apply_kernel,
                         cudaFuncAttributeMaxDynamicSharedMemorySize, AP_SMEM_BYTES);

    dim3 ggemm(HH / 128, MTOT / 128);   // (6, 25)
    dim3 gapply(HH / 128, BB);          // (6, 64)
    dim3 gsplitw((HH * HH / 4 + 255) / 256, 3);

    // 0) weights -> bf16 splits (W1,W2,Wa)
    split_weights_kernel<<<gsplitw, 256>>>(W1, W2, Wa);
    // 1) gather + PE (+ split of X)
    gather_pe_kernel<<<MTOT, HH / 4>>>(emb, ids);
    // 2) Wh1 = X @ W1 + b1 -> bf16 splits only (+ a1 score partials)
    gemm_bf16x3<<<ggemm, 256, SMEM_BYTES>>>(Ah, Al, Bh, Bl, b1, nullptr, MTOT, a1, Whh, Whl);
    // 3) GAT layer 1: softmax (once per dialogue) + tensor-core apply
    softmax_kernel<<<BB, 256>>>(adj, ab1);
    gat_apply_kernel<<<gapply, 256, AP_SMEM_BYTES>>>(Whh, Whl, nullptr, nullptr, Ah, Al);
    // 4) Wh2 = H1 @ W2 + b2 -> bf16 splits only (+ a2 score partials)
    gemm_bf16x3<<<ggemm, 256, SMEM_BYTES>>>(Ah, Al, Bh + WSZ, Bl + WSZ, b2, nullptr, MTOT, a2, Whh, Whl);
    // 5) GAT layer 2: softmax + apply (+ residual X) -> Hres + split
    softmax_kernel<<<BB, 256>>>(adj, ab2);
    gat_apply_kernel<<<gapply, 256, AP_SMEM_BYTES>>>(Whh, Whl, X, Hres, Ah, Al);
    // 6) T = Hres @ Wa + ba (fp32 out for pooling)
    gemm_bf16x3<<<ggemm, 256, SMEM_BYTES>>>(Ah, Al, Bh + 2*WSZ, Bl + 2*WSZ, ba, T, MTOT, nullptr, nullptr, nullptr);
    // 7+8) fused pooling + final linear
    pool_final_kernel<<<BB, 256>>>(T, v, Hres, Wl, bl, out);
}

// round 13
// speedup vs baseline: 1.2731x; 1.2731x over previous
#include <cuda_runtime.h>
#include <cuda_bf16.h>
#include <math.h>

#define BB 64
#define LL 512
#define HH 768
#define NN 50
#define OO 768
#define MTOT (BB*NN)   // 3200

// ---------------- scratch (device globals; no allocations allowed) ----------
__device__ float g_Hres[MTOT*HH];
__device__ float g_T[MTOT*HH];
__device__ float g_sp1[12*MTOT];   // partial a_src sums (per bn x warp_n)
__device__ float g_sp2[12*MTOT];   // partial a_dst sums
__device__ float g_D[BB*HH];
__device__ __nv_bfloat16 g_Xh[MTOT*HH];    // X split (kept for residual)
__device__ __nv_bfloat16 g_Xl[MTOT*HH];
__device__ __nv_bfloat16 g_Ah[MTOT*HH];    // GEMM A input splits (H1, Hres)
__device__ __nv_bfloat16 g_Al[MTOT*HH];
__device__ __nv_bfloat16 g_Whh[MTOT*HH];   // Wh output splits (for mma apply)
__device__ __nv_bfloat16 g_Whl[MTOT*HH];
__device__ __nv_bfloat16 g_Bh[3*HH*HH];    // W1,W2,Wa hi
__device__ __nv_bfloat16 g_Bl[3*HH*HH];    // W1,W2,Wa lo

__device__ __forceinline__ void split1(float v, __nv_bfloat16& h, __nv_bfloat16& l) {
    h = __float2bfloat16(v);
    l = __float2bfloat16(v - __bfloat162float(h));
}

#define CP16(dst, src) \
    asm volatile("cp.async.cg.shared.global [%0], [%1], 16;\n" :: "r"(dst), "l"(src))

__device__ __forceinline__ void ldsm4(unsigned* r, const void* p) {
    unsigned addr = (unsigned)__cvta_generic_to_shared(p);
    asm volatile("ldmatrix.sync.aligned.m8n8.x4.shared.b16 {%0,%1,%2,%3}, [%4];\n"
                 : "=r"(r[0]), "=r"(r[1]), "=r"(r[2]), "=r"(r[3]) : "r"(addr));
}
__device__ __forceinline__ void ldsm4t(unsigned* r, const void* p) {
    unsigned addr = (unsigned)__cvta_generic_to_shared(p);
    asm volatile("ldmatrix.sync.aligned.m8n8.x4.trans.shared.b16 {%0,%1,%2,%3}, [%4];\n"
                 : "=r"(r[0]), "=r"(r[1]), "=r"(r[2]), "=r"(r[3]) : "r"(addr));
}
__device__ __forceinline__ void mma16816(float* c, const unsigned* a, const unsigned* b) {
    asm volatile("mma.sync.aligned.m16n8k16.row.col.f32.bf16.bf16.f32 "
                 "{%0,%1,%2,%3}, {%4,%5,%6,%7}, {%8,%9}, {%0,%1,%2,%3};\n"
                 : "+f"(c[0]), "+f"(c[1]), "+f"(c[2]), "+f"(c[3])
                 : "r"(a[0]), "r"(a[1]), "r"(a[2]), "r"(a[3]),
                   "r"(b[0]), "r"(b[1]));
}

// ---------------- 0) split the 3 mma weight matrices -----------------------
__global__ void split_weights_kernel(const float* __restrict__ w0,
                                     const float* __restrict__ w1,
                                     const float* __restrict__ w2)
{
    const float* srcs[3] = {w0, w1, w2};
    int m = blockIdx.y;
    int i = blockIdx.x * blockDim.x + threadIdx.x;
    const int n4 = HH * HH / 4;
    if (i >= n4) return;
    float4 v = ((const float4*)srcs[m])[i];
    __nv_bfloat16 h0,h1,h2,h3,l0,l1,l2,l3;
    split1(v.x,h0,l0); split1(v.y,h1,l1); split1(v.z,h2,l2); split1(v.w,h3,l3);
    __nv_bfloat162* H = (__nv_bfloat162*)(g_Bh + (size_t)m * HH * HH);
    __nv_bfloat162* L = (__nv_bfloat162*)(g_Bl + (size_t)m * HH * HH);
    H[2*i]   = __nv_bfloat162(h0,h1);
    H[2*i+1] = __nv_bfloat162(h2,h3);
    L[2*i]   = __nv_bfloat162(l0,l1);
    L[2*i+1] = __nv_bfloat162(l2,l3);
}

// ---------------- 1) gather + sinusoidal PE -> bf16 split of X only --------
__global__ void gather_pe_kernel(const float* __restrict__ emb,
                                 const int* __restrict__ ids)
{
    int bn = blockIdx.x;
    int b = bn / NN, n = bn % NN;
    int h = threadIdx.x * 4;
    int id = ids[bn];
    float4 e = *(const float4*)(emb + ((size_t)b * LL + id) * HH + h);
    const float c = -logf(10000.0f) / (float)HH;
    float d0 = expf((float)h * c);
    float d1 = expf((float)(h + 2) * c);
    float a0 = (float)n * d0, a1 = (float)n * d1;
    e.x += sinf(a0); e.y += cosf(a0);
    e.z += sinf(a1); e.w += cosf(a1);
    size_t off = (size_t)bn * HH + h;
    __nv_bfloat16 h0,h1,h2,h3,l0,l1,l2,l3;
    split1(e.x,h0,l0); split1(e.y,h1,l1); split1(e.z,h2,l2); split1(e.w,h3,l3);
    *(__nv_bfloat162*)(g_Xh + off)     = __nv_bfloat162(h0,h1);
    *(__nv_bfloat162*)(g_Xh + off + 2) = __nv_bfloat162(h2,h3);
    *(__nv_bfloat162*)(g_Xl + off)     = __nv_bfloat162(l0,l1);
    *(__nv_bfloat162*)(g_Xl + off + 2) = __nv_bfloat162(l2,l3);
}

// ---------------- tensor-core GEMM (bf16x3 split, fp32 accum) --------------
// KC=32, 2-stage cp.async, 2 CTAs/SM (proven R7/R8 config).
#define KC 32
#define SA_ELEMS (2*128*40)
#define SB_ELEMS (2*32*136)
#define STAGE_ELEMS (SA_ELEMS + SB_ELEMS)   // 18944
#define SA_IDX(st,sp,r,c) ((size_t)(st)*STAGE_ELEMS + ((sp)*128 + (r))*40 + (c))
#define SB_IDX(st,sp,r,c) ((size_t)(st)*STAGE_ELEMS + SA_ELEMS + ((sp)*32 + (r))*136 + (c))
#define SMEM_BYTES (2 * STAGE_ELEMS * 2)    // 75776 B -> 2 CTAs/SM

__global__ __launch_bounds__(256, 2) void gemm_bf16x3(
    const __nv_bfloat16* __restrict__ Ah, const __nv_bfloat16* __restrict__ Al,
    const __nv_bfloat16* __restrict__ Bh, const __nv_bfloat16* __restrict__ Bl,
    const float* __restrict__ bias, float* __restrict__ C, int M,
    const float* __restrict__ avec,
    __nv_bfloat16* __restrict__ Ch, __nv_bfloat16* __restrict__ Cl)
{
    extern __shared__ __nv_bfloat16 sm[];
    const int tid = threadIdx.x;
    const int lane = tid & 31, wid = tid >> 5;
    const int warp_m = wid >> 1, warp_n = wid & 1;
    const int bm = blockIdx.y * 128, bn = blockIdx.x * 128;

    const int ar = tid >> 2, ac = (tid & 3) * 8;
    const int br = tid >> 4, bc = (tid & 15) * 8;
    const int rA0 = min(bm + ar, M - 1);
    const int rA1 = min(bm + ar + 64, M - 1);

    float acc[2][8][4] = {};
    const __nv_bfloat16* As[2] = {Ah, Al};
    const __nv_bfloat16* Bs[2] = {Bh, Bl};

    auto load_stage = [&](int st, int k0) {
        #pragma unroll
        for (int s = 0; s < 2; s++) {
            unsigned d0 = (unsigned)__cvta_generic_to_shared(&sm[SA_IDX(st, s, ar, ac)]);
            CP16(d0, As[s] + (size_t)rA0 * HH + k0 + ac);
            unsigned d1 = (unsigned)__cvta_generic_to_shared(&sm[SA_IDX(st, s, ar + 64, ac)]);
            CP16(d1, As[s] + (size_t)rA1 * HH + k0 + ac);
            unsigned e0 = (unsigned)__cvta_generic_to_shared(&sm[SB_IDX(st, s, br, bc)]);
            CP16(e0, Bs[s] + (size_t)(k0 + br) * HH + bn + bc);
            unsigned e1 = (unsigned)__cvta_generic_to_shared(&sm[SB_IDX(st, s, br + 16, bc)]);
            CP16(e1, Bs[s] + (size_t)(k0 + br + 16) * HH + bn + bc);
        }
        asm volatile("cp.async.commit_group;" ::: "memory");
    };

    load_stage(0, 0);

    const int lrow = lane & 15, lcol = (lane >> 4) * 8;
    const int NCH = HH / KC;   // 24

    for (int c = 0; c < NCH; c++) {
        asm volatile("cp.async.wait_group 0;" ::: "memory");
        __syncthreads();
        if (c + 1 < NCH) load_stage((c + 1) & 1, (c + 1) * KC);
        const int st = c & 1;

        #pragma unroll
        for (int ks = 0; ks < 2; ks++) {
            const int kb = ks * 16;
            unsigned a[2][2][4];
            #pragma unroll
            for (int mt = 0; mt < 2; mt++)
                #pragma unroll
                for (int s = 0; s < 2; s++)
                    ldsm4(a[s][mt], &sm[SA_IDX(st, s, warp_m * 32 + mt * 16 + lrow, kb + lcol)]);
            #pragma unroll
            for (int g = 0; g < 4; g++) {
                unsigned bh[4], bl[4];
                ldsm4t(bh, &sm[SB_IDX(st, 0, kb + lrow, warp_n * 64 + g * 16 + lcol)]);
                ldsm4t(bl, &sm[SB_IDX(st, 1, kb + lrow, warp_n * 64 + g * 16 + lcol)]);
                #pragma unroll
                for (int mt = 0; mt < 2; mt++) {
                    mma16816(acc[mt][2*g],   a[0][mt], bh);
                    mma16816(acc[mt][2*g],   a[0][mt], bl);
                    mma16816(acc[mt][2*g],   a[1][mt], bh);
                    mma16816(acc[mt][2*g+1], a[0][mt], bh + 2);
                    mma16816(acc[mt][2*g+1], a[0][mt], bl + 2);
                    mma16816(acc[mt][2*g+1], a[1][mt], bh + 2);
                }
            }
        }
    }

    // ---- epilogue ----
    const int er = bm + warp_m * 32 + (lane >> 2);
    const int ec = bn + warp_n * 64 + (lane & 3) * 2;
    float p1[2][2] = {}, p2[2][2] = {};
    #pragma unroll
    for (int mt = 0; mt < 2; mt++)
        #pragma unroll
        for (int nt = 0; nt < 8; nt++) {
            int r = er + mt * 16;
            int cc = ec + nt * 8;
            float b0 = bias[cc], b1 = bias[cc + 1];
            float v00 = acc[mt][nt][0] + b0, v01 = acc[mt][nt][1] + b1;
            float v10 = acc[mt][nt][2] + b0, v11 = acc[mt][nt][3] + b1;
            if (r < M) {
                size_t off = (size_t)r * HH + cc;
                if (C) { C[off] = v00; C[off + 1] = v01; }
                if (Ch) {
                    __nv_bfloat16 h0,l0,h1,l1;
                    split1(v00,h0,l0); split1(v01,h1,l1);
                    *(__nv_bfloat162*)(Ch + off) = __nv_bfloat162(h0,h1);
                    *(__nv_bfloat162*)(Cl + off) = __nv_bfloat162(l0,l1);
                }
            }
            if (r + 8 < M) {
                size_t off = (size_t)(r + 8) * HH + cc;
                if (C) { C[off] = v10; C[off + 1] = v11; }
                if (Ch) {
                    __nv_bfloat16 h0,l0,h1,l1;
                    split1(v10,h0,l0); split1(v11,h1,l1);
                    *(__nv_bfloat162*)(Ch + off) = __nv_bfloat162(h0,h1);
                    *(__nv_bfloat162*)(Cl + off) = __nv_bfloat162(l0,l1);
                }
            }
            if (avec) {
                float au0 = avec[cc], au1 = avec[cc + 1];
                float av0 = avec[HH + cc], av1 = avec[HH + cc + 1];
                p1[mt][0] += v00 * au0 + v01 * au1;
                p2[mt][0] += v00 * av0 + v01 * av1;
                p1[mt][1] += v10 * au0 + v11 * au1;
                p2[mt][1] += v10 * av0 + v11 * av1;
            }
        }
    if (avec) {
        #pragma unroll
        for (int mt = 0; mt < 2; mt++)
            #pragma unroll
            for (int h = 0; h < 2; h++) {
                #pragma unroll
                for (int o = 1; o <= 2; o <<= 1) {
                    p1[mt][h] += __shfl_xor_sync(~0u, p1[mt][h], o);
                    p2[mt][h] += __shfl_xor_sync(~0u, p2[mt][h], o);
                }
            }
        if ((lane & 3) == 0) {
            int slot = blockIdx.x * 2 + warp_n;
            #pragma unroll
            for (int mt = 0; mt < 2; mt++)
                #pragma unroll
                for (int h = 0; h < 2; h++) {
                    int r = er + mt * 16 + h * 8;
                    if (r < M) {
                        g_sp1[(size_t)slot * MTOT + r] = p1[mt][h];
                        g_sp2[(size_t)slot * MTOT + r] = p2[mt][h];
                    }
                }
        }
    }
}

// -- 3) GAT tail: reduce partials, masked softmax, bf16x3 mma apply, elu ----
// residual read from bf16 hi/lo pair (exact to 2^-17); Hres written fp32.
#define AP_ATT_H 0
#define AP_ATT_L 4608
#define AP_WH_H  9216
#define AP_WH_L  17920
#define AP_FLT   26624
#define AP_SMEM_BYTES (26624*2 + 512)   // 53760

__global__ __launch_bounds__(256, 2) void gat_apply_kernel(
    const __nv_bfloat16* __restrict__ Whh, const __nv_bfloat16* __restrict__ Whl,
    const int* __restrict__ adj, const float* __restrict__ ab,
    const __nv_bfloat16* __restrict__ residh, const __nv_bfloat16* __restrict__ residl,
    float* __restrict__ out_f32,
    __nv_bfloat16* __restrict__ hi, __nv_bfloat16* __restrict__ lo)
{
    extern __shared__ __nv_bfloat16 sm2[];
    float* asrc_s = (float*)(sm2 + AP_FLT);
    float* adst_s = asrc_s + 64;
    int b = blockIdx.y, ch = blockIdx.x;
    int t = threadIdx.x, lane = t & 31, w = t >> 5;

    {   // async load Wh hi/lo chunk [64 k-rows][128 cols], rows >= NN clamped
        int kr = t >> 2;
        int cg = (t & 3) * 8;
        int grow = b * NN + min(kr, NN - 1);
        const __nv_bfloat16* srch = Whh + (size_t)grow * HH + ch * 128;
        const __nv_bfloat16* srcl = Whl + (size_t)grow * HH + ch * 128;
        #pragma unroll
        for (int p = 0; p < 4; p++) {
            int col = cg + p * 32;
            unsigned dh = (unsigned)__cvta_generic_to_shared(&sm2[AP_WH_H + kr * 136 + col]);
            CP16(dh, srch + col);
            unsigned dl = (unsigned)__cvta_generic_to_shared(&sm2[AP_WH_L + kr * 136 + col]);
            CP16(dl, srcl + col);
        }
        asm volatile("cp.async.commit_group;\n" ::: "memory");
    }
    {   // zero ATT_H + ATT_L
        unsigned long long* z = (unsigned long long*)sm2;
        for (int i = t; i < 2304; i += 256) z[i] = 0ull;
    }
    if (t < 2 * NN) {   // reduce the 12 score partials
        int i = t % NN;
        const float* sp = (t < NN) ? g_sp1 : g_sp2;
        float s = 0.f;
        #pragma unroll
        for (int c = 0; c < 12; c++) s += sp[(size_t)c * MTOT + b * NN + i];
        ((t < NN) ? asrc_s : adst_s)[i] = s;
    }
    __syncthreads();

    float abv = *ab;
    for (int i = w; i < NN; i += 8) {
        float ai = asrc_s[i];
        const int* adjr = adj + ((size_t)b * NN + i) * NN;
        int j2 = lane + 32;
        float v0 = ai + adst_s[lane] + abv;
        v0 = v0 >= 0.f ? v0 : 0.3f * v0;
        float e0 = (adjr[lane] > 0) ? v0 : -1e30f;
        float e1 = -1e30f;
        if (j2 < NN) {
            float v1 = ai + adst_s[j2] + abv;
            v1 = v1 >= 0.f ? v1 : 0.3f * v1;
            e1 = (adjr[j2] > 0) ? v1 : -1e30f;
        }
        float m = fmaxf(e0, e1);
        #pragma unroll
        for (int o = 16; o; o >>= 1) m = fmaxf(m, __shfl_xor_sync(~0u, m, o));
        float x0 = expf(e0 - m);
        float x1 = (j2 < NN) ? expf(e1 - m) : 0.f;
        float s = x0 + x1;
        #pragma unroll
        for (int o = 16; o; o >>= 1) s += __shfl_xor_sync(~0u, s, o);
        float inv = 1.f / s;
        split1(x0 * inv, sm2[AP_ATT_H + i * 72 + lane], sm2[AP_ATT_L + i * 72 + lane]);
        if (j2 < NN)
            split1(x1 * inv, sm2[AP_ATT_H + i * 72 + j2], sm2[AP_ATT_L + i * 72 + j2]);
    }
    asm volatile("cp.async.wait_group 0;\n" ::: "memory");
    __syncthreads();

    const int lrow = lane & 15, lcol = (lane >> 4) * 8;
    const int n0 = w * 16;
    float acc[4][2][4] = {};
    #pragma unroll
    for (int kb = 0; kb < 64; kb += 16) {
        unsigned ah[4][4], al[4][4];
        #pragma unroll
        for (int mt = 0; mt < 4; mt++) {
            ldsm4(ah[mt], &sm2[AP_ATT_H + (mt * 16 + lrow) * 72 + kb + lcol]);
            ldsm4(al[mt], &sm2[AP_ATT_L + (mt * 16 + lrow) * 72 + kb + lcol]);
        }
        unsigned bh[4], bl[4];
        ldsm4t(bh, &sm2[AP_WH_H + (kb + lrow) * 136 + n0 + lcol]);
        ldsm4t(bl, &sm2[AP_WH_L + (kb + lrow) * 136 + n0 + lcol]);
        #pragma unroll
        for (int mt = 0; mt < 4; mt++) {
            mma16816(acc[mt][0], ah[mt], bh);
            mma16816(acc[mt][0], ah[mt], bl);
            mma16816(acc[mt][0], al[mt], bh);
            mma16816(acc[mt][1], ah[mt], bh + 2);
            mma16816(acc[mt][1], ah[mt], bl + 2);
            mma16816(acc[mt][1], al[mt], bh + 2);
        }
    }
    #pragma unroll
    for (int mt = 0; mt < 4; mt++)
        #pragma unroll
        for (int nt = 0; nt < 2; nt++) {
            int cc = ch * 128 + n0 + nt * 8 + (lane & 3) * 2;
            #pragma unroll
            for (int h = 0; h < 2; h++) {
                int row = mt * 16 + (lane >> 2) + h * 8;
                if (row < NN) {
                    float vx = acc[mt][nt][2*h], vy = acc[mt][nt][2*h + 1];
                    vx = vx > 0.f ? vx : expm1f(vx);
                    vy = vy > 0.f ? vy : expm1f(vy);
                    size_t off = ((size_t)b * NN + row) * HH + cc;
                    if (residh) {
                        __nv_bfloat162 rh = *(const __nv_bfloat162*)(residh + off);
                        __nv_bfloat162 rl = *(const __nv_bfloat162*)(residl + off);
                        vx += __bfloat162float(rh.x) + __bfloat162float(rl.x);
                        vy += __bfloat162float(rh.y) + __bfloat162float(rl.y);
                    }
                    if (out_f32) { out_f32[off] = vx; out_f32[off + 1] = vy; }
                    __nv_bfloat16 h0,l0,h1,l1;
                    split1(vx,h0,l0); split1(vy,h1,l1);
                    *(__nv_bfloat162*)(hi + off) = __nv_bfloat162(h0,h1);
                    *(__nv_bfloat162*)(lo + off) = __nv_bfloat162(l0,l1);
                }
            }
        }
}

// -------- 5) attention pooling -> fp32 D -----------------------------------
__global__ void pool_kernel(const float* __restrict__ T,
                            const float* __restrict__ v,
                            const float* __restrict__ Hres,
                            float* __restrict__ D)
{
    int b = blockIdx.x;
    int t = threadIdx.x, lane = t & 31, w = t >> 5;
    __shared__ float sc[NN];
    for (int n = w; n < NN; n += 8) {
        const float4* row = (const float4*)(T + ((size_t)b * NN + n) * HH);
        float s = 0.f;
        for (int c2 = lane; c2 < HH / 4; c2 += 32) {
            float4 x = row[c2];
            float4 u = ((const float4*)v)[c2];
            s += tanhf(x.x) * u.x + tanhf(x.y) * u.y +
                 tanhf(x.z) * u.z + tanhf(x.w) * u.w;
        }
        #pragma unroll
        for (int o = 16; o; o >>= 1) s += __shfl_xor_sync(~0u, s, o);
        if (lane == 0) sc[n] = s;
    }
    __syncthreads();
    if (t == 0) {
        float m = -1e30f;
        for (int n = 0; n < NN; n++) m = fmaxf(m, sc[n]);
        float s = 0.f;
        for (int n = 0; n < NN; n++) { sc[n] = expf(sc[n] - m); s += sc[n]; }
        float inv = 1.f / s;
        for (int n = 0; n < NN; n++) sc[n] *= inv;
    }
    __syncthreads();
    for (int h = t; h < HH; h += 256) {
        float acc = 0.f;
        #pragma unroll 5
        for (int n = 0; n < NN; n++)
            acc = fmaf(sc[n], Hres[((size_t)b * NN + n) * HH + h], acc);
        D[(size_t)b * HH + h] = acc;
    }
}

// -------- 6) final linear: out[64,768] = D @ Wl + bl (fp32, wide grid) -----
__global__ __launch_bounds__(128) void final_linear_kernel(
    const float* __restrict__ D, const float* __restrict__ W,
    const float* __restrict__ bias, float* __restrict__ out)
{
    int b = blockIdx.y;
    int o = blockIdx.x * 128 + threadIdx.x;
    __shared__ float Ds[HH];
    for (int i = threadIdx.x; i < HH; i += 128)
        Ds[i] = D[(size_t)b * HH + i];
    __syncthreads();
    float acc = 0.f;
    #pragma unroll 8
    for (int h = 0; h < HH; h++)
        acc = fmaf(Ds[h], W[(size_t)h * OO + o], acc);
    out[(size_t)b * OO + o] = acc + bias[o];
}

// ---------------- launch ----------------------------------------------------
extern "C" void kernel_launch(void* const* d_in, const int* in_sizes, int n_in,
                              void* d_out, int out_size)
{
    const float* emb = (const float*)d_in[0];
    const int*   ids = (const int*)  d_in[1];
    const int*   adj = (const int*)  d_in[2];
    const float* W1  = (const float*)d_in[3];
    const float* b1  = (const float*)d_in[4];
    const float* a1  = (const float*)d_in[5];
    const float* ab1 = (const float*)d_in[6];
    const float* W2  = (const float*)d_in[7];
    const float* b2  = (const float*)d_in[8];
    const float* a2  = (const float*)d_in[9];
    const float* ab2 = (const float*)d_in[10];
    const float* Wa  = (const float*)d_in[11];
    const float* ba  = (const float*)d_in[12];
    const float* v   = (const float*)d_in[13];
    const float* Wl  = (const float*)d_in[14];
    const float* bl  = (const float*)d_in[15];
    float* out = (float*)d_out;

    void *pHres, *pT, *pD, *pXh, *pXl, *pAh, *pAl, *pWhh, *pWhl, *pBh, *pBl;
    cudaGetSymbolAddress(&pHres, g_Hres);
    cudaGetSymbolAddress(&pT, g_T);
    cudaGetSymbolAddress(&pD, g_D);
    cudaGetSymbolAddress(&pXh, g_Xh);
    cudaGetSymbolAddress(&pXl, g_Xl);
    cudaGetSymbolAddress(&pAh, g_Ah);
    cudaGetSymbolAddress(&pAl, g_Al);
    cudaGetSymbolAddress(&pWhh, g_Whh);
    cudaGetSymbolAddress(&pWhl, g_Whl);
    cudaGetSymbolAddress(&pBh, g_Bh);
    cudaGetSymbolAddress(&pBl, g_Bl);
    float* Hres = (float*)pHres;
    float* T    = (float*)pT;
    float* D    = (float*)pD;
    __nv_bfloat16* Xh  = (__nv_bfloat16*)pXh;
    __nv_bfloat16* Xl  = (__nv_bfloat16*)pXl;
    __nv_bfloat16* Ah  = (__nv_bfloat16*)pAh;
    __nv_bfloat16* Al  = (__nv_bfloat16*)pAl;
    __nv_bfloat16* Whh = (__nv_bfloat16*)pWhh;
    __nv_bfloat16* Whl = (__nv_bfloat16*)pWhl;
    __nv_bfloat16* Bh  = (__nv_bfloat16*)pBh;
    __nv_bfloat16* Bl  = (__nv_bfloat16*)pBl;
    const size_t WSZ = (size_t)HH * HH;

    cudaFuncSetAttribute(gemm_bf16x3,
                         cudaFuncAttributeMaxDynamicSharedMemorySize, SMEM_BYTES);
    cudaFuncSetAttribute(gat_apply_kernel,
                         cudaFuncAttributeMaxDynamicSharedMemorySize, AP_SMEM_BYTES);

    dim3 ggemm(HH / 128, MTOT / 128);   // (6, 25)
    dim3 gapply(HH / 128, BB);          // (6, 64)
    dim3 gsplitw((HH * HH / 4 + 255) / 256, 3);
    dim3 gfinal(OO / 128, BB);          // (6, 64)

    // 0) weights -> bf16 splits (W1,W2,Wa)
    split_weights_kernel<<<gsplitw, 256>>>(W1, W2, Wa);
    // 1) gather + PE -> X split (bf16 only, no fp32 copy)
    gather_pe_kernel<<<MTOT, HH / 4>>>(emb, ids);
    // 2) Wh1 = X @ W1 + b1 -> bf16 splits only (+ a1 score partials)
    gemm_bf16x3<<<ggemm, 256, SMEM_BYTES>>>(Xh, Xl, Bh, Bl, b1, nullptr, MTOT, a1, Whh, Whl);
    // 3) GAT layer 1 tail (softmax + tensor-core apply) -> split(H1)
    gat_apply_kernel<<<gapply, 256, AP_SMEM_BYTES>>>(Whh, Whl, adj, ab1,
                                                     nullptr, nullptr, nullptr, Ah, Al);
    // 4) Wh2 = H1 @ W2 + b2 -> bf16 splits only (+ a2 score partials)
    gemm_bf16x3<<<ggemm, 256, SMEM_BYTES>>>(Ah, Al, Bh + WSZ, Bl + WSZ, b2, nullptr, MTOT, a2, Whh, Whl);
    // 5) GAT layer 2 tail (+ residual from X split) -> Hres fp32 + split
    gat_apply_kernel<<<gapply, 256, AP_SMEM_BYTES>>>(Whh, Whl, adj, ab2,
                                                     Xh, Xl, Hres, Ah, Al);
    // 6) T = Hres @ Wa + ba (fp32 out for pooling)
    gemm_bf16x3<<<ggemm, 256, SMEM_BYTES>>>(Ah, Al, Bh + 2*WSZ, Bl + 2*WSZ, ba, T, MTOT, nullptr, nullptr, nullptr);
    // 7) attention pooling -> fp32 D
    pool_kernel<<<BB, 256>>>(T, v, Hres, D);
    // 8) out = D @ Wl + bl (wide grid)
    final_linear_kernel<<<gfinal, 128>>>(D, Wl, bl, out);
}

// round 14
// speedup vs baseline: 1.2959x; 1.0178x over previous
#include <cuda_runtime.h>
#include <cuda_bf16.h>
#include <math.h>

#define BB 64
#define LL 512
#define HH 768
#define NN 50
#define OO 768
#define MTOT (BB*NN)   // 3200

// ---------------- scratch (device globals; no allocations allowed) ----------
__device__ float g_Hres[MTOT*HH];
__device__ float g_T[MTOT*HH];
__device__ float g_sp1[12*MTOT];   // partial a_src sums (per bn x warp_n)
__device__ float g_sp2[12*MTOT];   // partial a_dst sums
__device__ float g_D[BB*HH];
__device__ __nv_bfloat16 g_Xh[MTOT*HH];    // X split (kept for residual)
__device__ __nv_bfloat16 g_Xl[MTOT*HH];
__device__ __nv_bfloat16 g_Ah[MTOT*HH];    // GEMM A input splits (H1, Hres)
__device__ __nv_bfloat16 g_Al[MTOT*HH];
__device__ __nv_bfloat16 g_Whh[MTOT*HH];   // Wh output splits (for mma apply)
__device__ __nv_bfloat16 g_Whl[MTOT*HH];
__device__ __nv_bfloat16 g_Bh[3*HH*HH];    // W1,W2,Wa hi
__device__ __nv_bfloat16 g_Bl[3*HH*HH];    // W1,W2,Wa lo

__device__ __forceinline__ void split1(float v, __nv_bfloat16& h, __nv_bfloat16& l) {
    h = __float2bfloat16(v);
    l = __float2bfloat16(v - __bfloat162float(h));
}

#define CP16(dst, src) \
    asm volatile("cp.async.cg.shared.global [%0], [%1], 16;\n" :: "r"(dst), "l"(src))

__device__ __forceinline__ void ldsm4(unsigned* r, const void* p) {
    unsigned addr = (unsigned)__cvta_generic_to_shared(p);
    asm volatile("ldmatrix.sync.aligned.m8n8.x4.shared.b16 {%0,%1,%2,%3}, [%4];\n"
                 : "=r"(r[0]), "=r"(r[1]), "=r"(r[2]), "=r"(r[3]) : "r"(addr));
}
__device__ __forceinline__ void ldsm4t(unsigned* r, const void* p) {
    unsigned addr = (unsigned)__cvta_generic_to_shared(p);
    asm volatile("ldmatrix.sync.aligned.m8n8.x4.trans.shared.b16 {%0,%1,%2,%3}, [%4];\n"
                 : "=r"(r[0]), "=r"(r[1]), "=r"(r[2]), "=r"(r[3]) : "r"(addr));
}
__device__ __forceinline__ void mma16816(float* c, const unsigned* a, const unsigned* b) {
    asm volatile("mma.sync.aligned.m16n8k16.row.col.f32.bf16.bf16.f32 "
                 "{%0,%1,%2,%3}, {%4,%5,%6,%7}, {%8,%9}, {%0,%1,%2,%3};\n"
                 : "+f"(c[0]), "+f"(c[1]), "+f"(c[2]), "+f"(c[3])
                 : "r"(a[0]), "r"(a[1]), "r"(a[2]), "r"(a[3]),
                   "r"(b[0]), "r"(b[1]));
}

// ---------------- 0) split the 3 mma weight matrices -----------------------
__global__ void split_weights_kernel(const float* __restrict__ w0,
                                     const float* __restrict__ w1,
                                     const float* __restrict__ w2)
{
    const float* srcs[3] = {w0, w1, w2};
    int m = blockIdx.y;
    int i = blockIdx.x * blockDim.x + threadIdx.x;
    const int n4 = HH * HH / 4;
    if (i >= n4) return;
    float4 v = ((const float4*)srcs[m])[i];
    __nv_bfloat16 h0,h1,h2,h3,l0,l1,l2,l3;
    split1(v.x,h0,l0); split1(v.y,h1,l1); split1(v.z,h2,l2); split1(v.w,h3,l3);
    __nv_bfloat162* H = (__nv_bfloat162*)(g_Bh + (size_t)m * HH * HH);
    __nv_bfloat162* L = (__nv_bfloat162*)(g_Bl + (size_t)m * HH * HH);
    H[2*i]   = __nv_bfloat162(h0,h1);
    H[2*i+1] = __nv_bfloat162(h2,h3);
    L[2*i]   = __nv_bfloat162(l0,l1);
    L[2*i+1] = __nv_bfloat162(l2,l3);
}

// ---------------- 1) gather + sinusoidal PE -> bf16 split of X only --------
__global__ void gather_pe_kernel(const float* __restrict__ emb,
                                 const int* __restrict__ ids)
{
    int bn = blockIdx.x;
    int b = bn / NN, n = bn % NN;
    int h = threadIdx.x * 4;
    int id = ids[bn];
    float4 e = *(const float4*)(emb + ((size_t)b * LL + id) * HH + h);
    const float c = -logf(10000.0f) / (float)HH;
    float d0 = expf((float)h * c);
    float d1 = expf((float)(h + 2) * c);
    float a0 = (float)n * d0, a1 = (float)n * d1;
    e.x += sinf(a0); e.y += cosf(a0);
    e.z += sinf(a1); e.w += cosf(a1);
    size_t off = (size_t)bn * HH + h;
    __nv_bfloat16 h0,h1,h2,h3,l0,l1,l2,l3;
    split1(e.x,h0,l0); split1(e.y,h1,l1); split1(e.z,h2,l2); split1(e.w,h3,l3);
    *(__nv_bfloat162*)(g_Xh + off)     = __nv_bfloat162(h0,h1);
    *(__nv_bfloat162*)(g_Xh + off + 2) = __nv_bfloat162(h2,h3);
    *(__nv_bfloat162*)(g_Xl + off)     = __nv_bfloat162(l0,l1);
    *(__nv_bfloat162*)(g_Xl + off + 2) = __nv_bfloat162(l2,l3);
}

// ---------------- tensor-core GEMM (bf16x3 split, fp32 accum) --------------
// KC=32, 2-stage cp.async, 2 CTAs/SM (proven config).
#define KC 32
#define SA_ELEMS (2*128*40)
#define SB_ELEMS (2*32*136)
#define STAGE_ELEMS (SA_ELEMS + SB_ELEMS)   // 18944
#define SA_IDX(st,sp,r,c) ((size_t)(st)*STAGE_ELEMS + ((sp)*128 + (r))*40 + (c))
#define SB_IDX(st,sp,r,c) ((size_t)(st)*STAGE_ELEMS + SA_ELEMS + ((sp)*32 + (r))*136 + (c))
#define SMEM_BYTES (2 * STAGE_ELEMS * 2)    // 75776 B -> 2 CTAs/SM

__global__ __launch_bounds__(256, 2) void gemm_bf16x3(
    const __nv_bfloat16* __restrict__ Ah, const __nv_bfloat16* __restrict__ Al,
    const __nv_bfloat16* __restrict__ Bh, const __nv_bfloat16* __restrict__ Bl,
    const float* __restrict__ bias, float* __restrict__ C, int M,
    const float* __restrict__ avec,
    __nv_bfloat16* __restrict__ Ch, __nv_bfloat16* __restrict__ Cl)
{
    extern __shared__ __nv_bfloat16 sm[];
    const int tid = threadIdx.x;
    const int lane = tid & 31, wid = tid >> 5;
    const int warp_m = wid >> 1, warp_n = wid & 1;
    const int bm = blockIdx.y * 128, bn = blockIdx.x * 128;

    const int ar = tid >> 2, ac = (tid & 3) * 8;
    const int br = tid >> 4, bc = (tid & 15) * 8;
    const int rA0 = min(bm + ar, M - 1);
    const int rA1 = min(bm + ar + 64, M - 1);

    float acc[2][8][4] = {};
    const __nv_bfloat16* As[2] = {Ah, Al};
    const __nv_bfloat16* Bs[2] = {Bh, Bl};

    auto load_stage = [&](int st, int k0) {
        #pragma unroll
        for (int s = 0; s < 2; s++) {
            unsigned d0 = (unsigned)__cvta_generic_to_shared(&sm[SA_IDX(st, s, ar, ac)]);
            CP16(d0, As[s] + (size_t)rA0 * HH + k0 + ac);
            unsigned d1 = (unsigned)__cvta_generic_to_shared(&sm[SA_IDX(st, s, ar + 64, ac)]);
            CP16(d1, As[s] + (size_t)rA1 * HH + k0 + ac);
            unsigned e0 = (unsigned)__cvta_generic_to_shared(&sm[SB_IDX(st, s, br, bc)]);
            CP16(e0, Bs[s] + (size_t)(k0 + br) * HH + bn + bc);
            unsigned e1 = (unsigned)__cvta_generic_to_shared(&sm[SB_IDX(st, s, br + 16, bc)]);
            CP16(e1, Bs[s] + (size_t)(k0 + br + 16) * HH + bn + bc);
        }
        asm volatile("cp.async.commit_group;" ::: "memory");
    };

    load_stage(0, 0);

    const int lrow = lane & 15, lcol = (lane >> 4) * 8;
    const int NCH = HH / KC;   // 24

    for (int c = 0; c < NCH; c++) {
        asm volatile("cp.async.wait_group 0;" ::: "memory");
        __syncthreads();
        if (c + 1 < NCH) load_stage((c + 1) & 1, (c + 1) * KC);
        const int st = c & 1;

        #pragma unroll
        for (int ks = 0; ks < 2; ks++) {
            const int kb = ks * 16;
            unsigned a[2][2][4];
            #pragma unroll
            for (int mt = 0; mt < 2; mt++)
                #pragma unroll
                for (int s = 0; s < 2; s++)
                    ldsm4(a[s][mt], &sm[SA_IDX(st, s, warp_m * 32 + mt * 16 + lrow, kb + lcol)]);
            #pragma unroll
            for (int g = 0; g < 4; g++) {
                unsigned bh[4], bl[4];
                ldsm4t(bh, &sm[SB_IDX(st, 0, kb + lrow, warp_n * 64 + g * 16 + lcol)]);
                ldsm4t(bl, &sm[SB_IDX(st, 1, kb + lrow, warp_n * 64 + g * 16 + lcol)]);
                #pragma unroll
                for (int mt = 0; mt < 2; mt++) {
                    mma16816(acc[mt][2*g],   a[0][mt], bh);
                    mma16816(acc[mt][2*g],   a[0][mt], bl);
                    mma16816(acc[mt][2*g],   a[1][mt], bh);
                    mma16816(acc[mt][2*g+1], a[0][mt], bh + 2);
                    mma16816(acc[mt][2*g+1], a[0][mt], bl + 2);
                    mma16816(acc[mt][2*g+1], a[1][mt], bh + 2);
                }
            }
        }
    }

    // ---- epilogue ----
    const int er = bm + warp_m * 32 + (lane >> 2);
    const int ec = bn + warp_n * 64 + (lane & 3) * 2;
    float p1[2][2] = {}, p2[2][2] = {};
    #pragma unroll
    for (int mt = 0; mt < 2; mt++)
        #pragma unroll
        for (int nt = 0; nt < 8; nt++) {
            int r = er + mt * 16;
            int cc = ec + nt * 8;
            float b0 = bias[cc], b1 = bias[cc + 1];
            float v00 = acc[mt][nt][0] + b0, v01 = acc[mt][nt][1] + b1;
            float v10 = acc[mt][nt][2] + b0, v11 = acc[mt][nt][3] + b1;
            if (r < M) {
                size_t off = (size_t)r * HH + cc;
                if (C) { C[off] = v00; C[off + 1] = v01; }
                if (Ch) {
                    __nv_bfloat16 h0,l0,h1,l1;
                    split1(v00,h0,l0); split1(v01,h1,l1);
                    *(__nv_bfloat162*)(Ch + off) = __nv_bfloat162(h0,h1);
                    *(__nv_bfloat162*)(Cl + off) = __nv_bfloat162(l0,l1);
                }
            }
            if (r + 8 < M) {
                size_t off = (size_t)(r + 8) * HH + cc;
                if (C) { C[off] = v10; C[off + 1] = v11; }
                if (Ch) {
                    __nv_bfloat16 h0,l0,h1,l1;
                    split1(v10,h0,l0); split1(v11,h1,l1);
                    *(__nv_bfloat162*)(Ch + off) = __nv_bfloat162(h0,h1);
                    *(__nv_bfloat162*)(Cl + off) = __nv_bfloat162(l0,l1);
                }
            }
            if (avec) {
                float au0 = avec[cc], au1 = avec[cc + 1];
                float av0 = avec[HH + cc], av1 = avec[HH + cc + 1];
                p1[mt][0] += v00 * au0 + v01 * au1;
                p2[mt][0] += v00 * av0 + v01 * av1;
                p1[mt][1] += v10 * au0 + v11 * au1;
                p2[mt][1] += v10 * av0 + v11 * av1;
            }
        }
    if (avec) {
        #pragma unroll
        for (int mt = 0; mt < 2; mt++)
            #pragma unroll
            for (int h = 0; h < 2; h++) {
                #pragma unroll
                for (int o = 1; o <= 2; o <<= 1) {
                    p1[mt][h] += __shfl_xor_sync(~0u, p1[mt][h], o);
                    p2[mt][h] += __shfl_xor_sync(~0u, p2[mt][h], o);
                }
            }
        if ((lane & 3) == 0) {
            int slot = blockIdx.x * 2 + warp_n;
            #pragma unroll
            for (int mt = 0; mt < 2; mt++)
                #pragma unroll
                for (int h = 0; h < 2; h++) {
                    int r = er + mt * 16 + h * 8;
                    if (r < M) {
                        g_sp1[(size_t)slot * MTOT + r] = p1[mt][h];
                        g_sp2[(size_t)slot * MTOT + r] = p2[mt][h];
                    }
                }
        }
    }
}

// -- 3) GAT tail: reduce partials, masked softmax, bf16x3 mma apply, elu ----
// N=256 per CTA (grid (3,64) = 192 CTAs = single wave at 2 CTAs/SM).
// smem (bf16 elems): ATT_H 0 (64x72), ATT_L 4608, WH_H 9216 (64x264),
//                    WH_L 26112, floats @ 43008
#define AP_ATT_H 0
#define AP_ATT_L 4608
#define AP_WH_H  9216
#define AP_WHSTR 264
#define AP_WH_L  26112
#define AP_FLT   43008
#define AP_SMEM_BYTES (43008*2 + 512)   // 86528 B -> 2 CTAs/SM (173 KB < 227 KB)

__global__ __launch_bounds__(256, 2) void gat_apply_kernel(
    const __nv_bfloat16* __restrict__ Whh, const __nv_bfloat16* __restrict__ Whl,
    const int* __restrict__ adj, const float* __restrict__ ab,
    const __nv_bfloat16* __restrict__ residh, const __nv_bfloat16* __restrict__ residl,
    float* __restrict__ out_f32,
    __nv_bfloat16* __restrict__ hi, __nv_bfloat16* __restrict__ lo)
{
    extern __shared__ __nv_bfloat16 sm2[];
    float* asrc_s = (float*)(sm2 + AP_FLT);
    float* adst_s = asrc_s + 64;
    int b = blockIdx.y, ch = blockIdx.x;   // ch: 256-col chunk (0..2)
    int t = threadIdx.x, lane = t & 31, w = t >> 5;

    {   // async load Wh hi/lo chunk [64 k-rows][256 cols], rows >= NN clamped
        int kr = t >> 2;
        int cg = (t & 3) * 8;
        int grow = b * NN + min(kr, NN - 1);
        const __nv_bfloat16* srch = Whh + (size_t)grow * HH + ch * 256;
        const __nv_bfloat16* srcl = Whl + (size_t)grow * HH + ch * 256;
        #pragma unroll
        for (int p = 0; p < 8; p++) {
            int col = cg + p * 32;
            unsigned dh = (unsigned)__cvta_generic_to_shared(&sm2[AP_WH_H + kr * AP_WHSTR + col]);
            CP16(dh, srch + col);
            unsigned dl = (unsigned)__cvta_generic_to_shared(&sm2[AP_WH_L + kr * AP_WHSTR + col]);
            CP16(dl, srcl + col);
        }
        asm volatile("cp.async.commit_group;\n" ::: "memory");
    }
    {   // zero ATT_H + ATT_L (2*4608 bf16 = 2304 u64)
        unsigned long long* z = (unsigned long long*)sm2;
        for (int i = t; i < 2304; i += 256) z[i] = 0ull;
    }
    if (t < 2 * NN) {   // reduce the 12 score partials
        int i = t % NN;
        const float* sp = (t < NN) ? g_sp1 : g_sp2;
        float s = 0.f;
        #pragma unroll
        for (int c = 0; c < 12; c++) s += sp[(size_t)c * MTOT + b * NN + i];
        ((t < NN) ? asrc_s : adst_s)[i] = s;
    }
    __syncthreads();

    float abv = *ab;
    for (int i = w; i < NN; i += 8) {
        float ai = asrc_s[i];
        const int* adjr = adj + ((size_t)b * NN + i) * NN;
        int j2 = lane + 32;
        float v0 = ai + adst_s[lane] + abv;
        v0 = v0 >= 0.f ? v0 : 0.3f * v0;
        float e0 = (adjr[lane] > 0) ? v0 : -1e30f;
        float e1 = -1e30f;
        if (j2 < NN) {
            float v1 = ai + adst_s[j2] + abv;
            v1 = v1 >= 0.f ? v1 : 0.3f * v1;
            e1 = (adjr[j2] > 0) ? v1 : -1e30f;
        }
        float m = fmaxf(e0, e1);
        #pragma unroll
        for (int o = 16; o; o >>= 1) m = fmaxf(m, __shfl_xor_sync(~0u, m, o));
        float x0 = expf(e0 - m);
        float x1 = (j2 < NN) ? expf(e1 - m) : 0.f;
        float s = x0 + x1;
        #pragma unroll
        for (int o = 16; o; o >>= 1) s += __shfl_xor_sync(~0u, s, o);
        float inv = 1.f / s;
        split1(x0 * inv, sm2[AP_ATT_H + i * 72 + lane], sm2[AP_ATT_L + i * 72 + lane]);
        if (j2 < NN)
            split1(x1 * inv, sm2[AP_ATT_H + i * 72 + j2], sm2[AP_ATT_L + i * 72 + j2]);
    }
    asm volatile("cp.async.wait_group 0;\n" ::: "memory");
    __syncthreads();

    // mma: [64x64] att (hi/lo) @ [64 x 32-per-warp] Wh (hi/lo), bf16x3
    const int lrow = lane & 15, lcol = (lane >> 4) * 8;
    const int n0 = w * 32;
    float acc[4][4][4] = {};
    #pragma unroll
    for (int kb = 0; kb < 64; kb += 16) {
        unsigned ah[4][4], al[4][4];
        #pragma unroll
        for (int mt = 0; mt < 4; mt++) {
            ldsm4(ah[mt], &sm2[AP_ATT_H + (mt * 16 + lrow) * 72 + kb + lcol]);
            ldsm4(al[mt], &sm2[AP_ATT_L + (mt * 16 + lrow) * 72 + kb + lcol]);
        }
        #pragma unroll
        for (int g = 0; g < 2; g++) {
            unsigned bh[4], bl[4];
            ldsm4t(bh, &sm2[AP_WH_H + (kb + lrow) * AP_WHSTR + n0 + g * 16 + lcol]);
            ldsm4t(bl, &sm2[AP_WH_L + (kb + lrow) * AP_WHSTR + n0 + g * 16 + lcol]);
            #pragma unroll
            for (int mt = 0; mt < 4; mt++) {
                mma16816(acc[mt][2*g],   ah[mt], bh);
                mma16816(acc[mt][2*g],   ah[mt], bl);
                mma16816(acc[mt][2*g],   al[mt], bh);
                mma16816(acc[mt][2*g+1], ah[mt], bh + 2);
                mma16816(acc[mt][2*g+1], ah[mt], bl + 2);
                mma16816(acc[mt][2*g+1], al[mt], bh + 2);
            }
        }
    }
    #pragma unroll
    for (int mt = 0; mt < 4; mt++)
        #pragma unroll
        for (int nt = 0; nt < 4; nt++) {
            int cc = ch * 256 + n0 + nt * 8 + (lane & 3) * 2;
            #pragma unroll
            for (int h = 0; h < 2; h++) {
                int row = mt * 16 + (lane >> 2) + h * 8;
                if (row < NN) {
                    float vx = acc[mt][nt][2*h], vy = acc[mt][nt][2*h + 1];
                    vx = vx > 0.f ? vx : expm1f(vx);
                    vy = vy > 0.f ? vy : expm1f(vy);
                    size_t off = ((size_t)b * NN + row) * HH + cc;
                    if (residh) {
                        __nv_bfloat162 rh = *(const __nv_bfloat162*)(residh + off);
                        __nv_bfloat162 rl = *(const __nv_bfloat162*)(residl + off);
                        vx += __bfloat162float(rh.x) + __bfloat162float(rl.x);
                        vy += __bfloat162float(rh.y) + __bfloat162float(rl.y);
                    }
                    if (out_f32) { out_f32[off] = vx; out_f32[off + 1] = vy; }
                    __nv_bfloat16 h0,l0,h1,l1;
                    split1(vx,h0,l0); split1(vy,h1,l1);
                    *(__nv_bfloat162*)(hi + off) = __nv_bfloat162(h0,h1);
                    *(__nv_bfloat162*)(lo + off) = __nv_bfloat162(l0,l1);
                }
            }
        }
}

// -------- 5) attention pooling -> fp32 D -----------------------------------
__global__ void pool_kernel(const float* __restrict__ T,
                            const float* __restrict__ v,
                            const float* __restrict__ Hres,
                            float* __restrict__ D)
{
    int b = blockIdx.x;
    int t = threadIdx.x, lane = t & 31, w = t >> 5;
    __shared__ float sc[NN];
    for (int n = w; n < NN; n += 8) {
        const float4* row = (const float4*)(T + ((size_t)b * NN + n) * HH);
        float s = 0.f;
        for (int c2 = lane; c2 < HH / 4; c2 += 32) {
            float4 x = row[c2];
            float4 u = ((const float4*)v)[c2];
            s += tanhf(x.x) * u.x + tanhf(x.y) * u.y +
                 tanhf(x.z) * u.z + tanhf(x.w) * u.w;
        }
        #pragma unroll
        for (int o = 16; o; o >>= 1) s += __shfl_xor_sync(~0u, s, o);
        if (lane == 0) sc[n] = s;
    }
    __syncthreads();
    if (t == 0) {
        float m = -1e30f;
        for (int n = 0; n < NN; n++) m = fmaxf(m, sc[n]);
        float s = 0.f;
        for (int n = 0; n < NN; n++) { sc[n] = expf(sc[n] - m); s += sc[n]; }
        float inv = 1.f / s;
        for (int n = 0; n < NN; n++) sc[n] *= inv;
    }
    __syncthreads();
    for (int h = t; h < HH; h += 256) {
        float acc = 0.f;
        #pragma unroll 5
        for (int n = 0; n < NN; n++)
            acc = fmaf(sc[n], Hres[((size_t)b * NN + n) * HH + h], acc);
        D[(size_t)b * HH + h] = acc;
    }
}

// -------- 6) final linear: out[64,768] = D @ Wl + bl (fp32, wide grid) -----
__global__ __launch_bounds__(128) void final_linear_kernel(
    const float* __restrict__ D, const float* __restrict__ W,
    const float* __restrict__ bias, float* __restrict__ out)
{
    int b = blockIdx.y;
    int o = blockIdx.x * 128 + threadIdx.x;
    __shared__ float Ds[HH];
    for (int i = threadIdx.x; i < HH; i += 128)
        Ds[i] = D[(size_t)b * HH + i];
    __syncthreads();
    float acc = 0.f;
    #pragma unroll 8
    for (int h = 0; h < HH; h++)
        acc = fmaf(Ds[h], W[(size_t)h * OO + o], acc);
    out[(size_t)b * OO + o] = acc + bias[o];
}

// ---------------- launch ----------------------------------------------------
extern "C" void kernel_launch(void* const* d_in, const int* in_sizes, int n_in,
                              void* d_out, int out_size)
{
    const float* emb = (const float*)d_in[0];
    const int*   ids = (const int*)  d_in[1];
    const int*   adj = (const int*)  d_in[2];
    const float* W1  = (const float*)d_in[3];
    const float* b1  = (const float*)d_in[4];
    const float* a1  = (const float*)d_in[5];
    const float* ab1 = (const float*)d_in[6];
    const float* W2  = (const float*)d_in[7];
    const float* b2  = (const float*)d_in[8];
    const float* a2  = (const float*)d_in[9];
    const float* ab2 = (const float*)d_in[10];
    const float* Wa  = (const float*)d_in[11];
    const float* ba  = (const float*)d_in[12];
    const float* v   = (const float*)d_in[13];
    const float* Wl  = (const float*)d_in[14];
    const float* bl  = (const float*)d_in[15];
    float* out = (float*)d_out;

    void *pHres, *pT, *pD, *pXh, *pXl, *pAh, *pAl, *pWhh, *pWhl, *pBh, *pBl;
    cudaGetSymbolAddress(&pHres, g_Hres);
    cudaGetSymbolAddress(&pT, g_T);
    cudaGetSymbolAddress(&pD, g_D);
    cudaGetSymbolAddress(&pXh, g_Xh);
    cudaGetSymbolAddress(&pXl, g_Xl);
    cudaGetSymbolAddress(&pAh, g_Ah);
    cudaGetSymbolAddress(&pAl, g_Al);
    cudaGetSymbolAddress(&pWhh, g_Whh);
    cudaGetSymbolAddress(&pWhl, g_Whl);
    cudaGetSymbolAddress(&pBh, g_Bh);
    cudaGetSymbolAddress(&pBl, g_Bl);
    float* Hres = (float*)pHres;
    float* T    = (float*)pT;
    float* D    = (float*)pD;
    __nv_bfloat16* Xh  = (__nv_bfloat16*)pXh;
    __nv_bfloat16* Xl  = (__nv_bfloat16*)pXl;
    __nv_bfloat16* Ah  = (__nv_bfloat16*)pAh;
    __nv_bfloat16* Al  = (__nv_bfloat16*)pAl;
    __nv_bfloat16* Whh = (__nv_bfloat16*)pWhh;
    __nv_bfloat16* Whl = (__nv_bfloat16*)pWhl;
    __nv_bfloat16* Bh  = (__nv_bfloat16*)pBh;
    __nv_bfloat16* Bl  = (__nv_bfloat16*)pBl;
    const size_t WSZ = (size_t)HH * HH;

    cudaFuncSetAttribute(gemm_bf16x3,
                         cudaFuncAttributeMaxDynamicSharedMemorySize, SMEM_BYTES);
    cudaFuncSetAttribute(gat_apply_kernel,
                         cudaFuncAttributeMaxDynamicSharedMemorySize, AP_SMEM_BYTES);

    dim3 ggemm(HH / 128, MTOT / 128);   // (6, 25)
    dim3 gapply(HH / 256, BB);          // (3, 64) = 192 CTAs (single wave)
    dim3 gsplitw((HH * HH / 4 + 255) / 256, 3);
    dim3 gfinal(OO / 128, BB);          // (6, 64)

    // 0) weights -> bf16 splits (W1,W2,Wa)
    split_weights_kernel<<<gsplitw, 256>>>(W1, W2, Wa);
    // 1) gather + PE -> X split (bf16 only)
    gather_pe_kernel<<<MTOT, HH / 4>>>(emb, ids);
    // 2) Wh1 = X @ W1 + b1 -> bf16 splits only (+ a1 score partials)
    gemm_bf16x3<<<ggemm, 256, SMEM_BYTES>>>(Xh, Xl, Bh, Bl, b1, nullptr, MTOT, a1, Whh, Whl);
    // 3) GAT layer 1 tail (softmax + tensor-core apply, N=256) -> split(H1)
    gat_apply_kernel<<<gapply, 256, AP_SMEM_BYTES>>>(Whh, Whl, adj, ab1,
                                                     nullptr, nullptr, nullptr, Ah, Al);
    // 4) Wh2 = H1 @ W2 + b2 -> bf16 splits only (+ a2 score partials)
    gemm_bf16x3<<<ggemm, 256, SMEM_BYTES>>>(Ah, Al, Bh + WSZ, Bl + WSZ, b2, nullptr, MTOT, a2, Whh, Whl);
    // 5) GAT layer 2 tail (+ residual from X split) -> Hres fp32 + split
    gat_apply_kernel<<<gapply, 256, AP_SMEM_BYTES>>>(Whh, Whl, adj, ab2,
                                                     Xh, Xl, Hres, Ah, Al);
    // 6) T = Hres @ Wa + ba (fp32 out for pooling)
    gemm_bf16x3<<<ggemm, 256, SMEM_BYTES>>>(Ah, Al, Bh + 2*WSZ, Bl + 2*WSZ, ba, T, MTOT, nullptr, nullptr, nullptr);
    // 7) attention pooling -> fp32 D
    pool_kernel<<<BB, 256>>>(T, v, Hres, D);
    // 8) out = D @ Wl + bl (wide grid)
    final_linear_kernel<<<gfinal, 128>>>(D, Wl, bl, out);
}

// round 15
// speedup vs baseline: 1.6288x; 1.2569x over previous
#include <cuda_runtime.h>
#include <cuda_bf16.h>
#include <math.h>

#define BB 64
#define LL 512
#define HH 768
#define NN 50
#define OO 768
#define MTOT (BB*NN)   // 3200

// ---------------- scratch (device globals; no allocations allowed) ----------
__device__ float g_sp1[12*MTOT];   // partial score sums (per bn x warp_n)
__device__ float g_sp2[12*MTOT];
__device__ float g_D[BB*HH];
__device__ __nv_bfloat16 g_Xh[MTOT*HH];    // X split (kept for residual)
__device__ __nv_bfloat16 g_Xl[MTOT*HH];
__device__ __nv_bfloat16 g_Ah[MTOT*HH];    // GEMM A input splits (H1, Hres)
__device__ __nv_bfloat16 g_Al[MTOT*HH];
__device__ __nv_bfloat16 g_Whh[MTOT*HH];   // Wh output splits (for mma apply)
__device__ __nv_bfloat16 g_Whl[MTOT*HH];
__device__ __nv_bfloat16 g_Bh[3*HH*HH];    // W1,W2,Wa hi
__device__ __nv_bfloat16 g_Bl[3*HH*HH];    // W1,W2,Wa lo

__device__ __forceinline__ void split1(float v, __nv_bfloat16& h, __nv_bfloat16& l) {
    h = __float2bfloat16(v);
    l = __float2bfloat16(v - __bfloat162float(h));
}

#define CP16(dst, src) \
    asm volatile("cp.async.cg.shared.global [%0], [%1], 16;\n" :: "r"(dst), "l"(src))

__device__ __forceinline__ void ldsm4(unsigned* r, const void* p) {
    unsigned addr = (unsigned)__cvta_generic_to_shared(p);
    asm volatile("ldmatrix.sync.aligned.m8n8.x4.shared.b16 {%0,%1,%2,%3}, [%4];\n"
                 : "=r"(r[0]), "=r"(r[1]), "=r"(r[2]), "=r"(r[3]) : "r"(addr));
}
__device__ __forceinline__ void ldsm4t(unsigned* r, const void* p) {
    unsigned addr = (unsigned)__cvta_generic_to_shared(p);
    asm volatile("ldmatrix.sync.aligned.m8n8.x4.trans.shared.b16 {%0,%1,%2,%3}, [%4];\n"
                 : "=r"(r[0]), "=r"(r[1]), "=r"(r[2]), "=r"(r[3]) : "r"(addr));
}
__device__ __forceinline__ void mma16816(float* c, const unsigned* a, const unsigned* b) {
    asm volatile("mma.sync.aligned.m16n8k16.row.col.f32.bf16.bf16.f32 "
                 "{%0,%1,%2,%3}, {%4,%5,%6,%7}, {%8,%9}, {%0,%1,%2,%3};\n"
                 : "+f"(c[0]), "+f"(c[1]), "+f"(c[2]), "+f"(c[3])
                 : "r"(a[0]), "r"(a[1]), "r"(a[2]), "r"(a[3]),
                   "r"(b[0]), "r"(b[1]));
}

// ---- 0+1) fused prep: gather+PE (blocks < MTOT) and weight splits ---------
#define SPLITW_BLOCKS 576   // HH*HH/4/256
__global__ void prep_kernel(const float* __restrict__ emb,
                            const int* __restrict__ ids,
                            const float* __restrict__ w0,
                            const float* __restrict__ w1,
                            const float* __restrict__ w2)
{
    if (blockIdx.x < MTOT) {
        int t = threadIdx.x;
        if (t >= HH / 4) return;
        int bn = blockIdx.x;
        int b = bn / NN, n = bn % NN;
        int h = t * 4;
        int id = ids[bn];
        float4 e = *(const float4*)(emb + ((size_t)b * LL + id) * HH + h);
        const float c = -logf(10000.0f) / (float)HH;
        float d0 = expf((float)h * c);
        float d1 = expf((float)(h + 2) * c);
        float a0 = (float)n * d0, a1 = (float)n * d1;
        e.x += sinf(a0); e.y += cosf(a0);
        e.z += sinf(a1); e.w += cosf(a1);
        size_t off = (size_t)bn * HH + h;
        __nv_bfloat16 h0,h1,h2,h3,l0,l1,l2,l3;
        split1(e.x,h0,l0); split1(e.y,h1,l1); split1(e.z,h2,l2); split1(e.w,h3,l3);
        *(__nv_bfloat162*)(g_Xh + off)     = __nv_bfloat162(h0,h1);
        *(__nv_bfloat162*)(g_Xh + off + 2) = __nv_bfloat162(h2,h3);
        *(__nv_bfloat162*)(g_Xl + off)     = __nv_bfloat162(l0,l1);
        *(__nv_bfloat162*)(g_Xl + off + 2) = __nv_bfloat162(l2,l3);
    } else {
        const float* srcs[3] = {w0, w1, w2};
        int bid = blockIdx.x - MTOT;
        int m = bid / SPLITW_BLOCKS;
        int i = (bid % SPLITW_BLOCKS) * 256 + threadIdx.x;
        float4 v = ((const float4*)srcs[m])[i];
        __nv_bfloat16 h0,h1,h2,h3,l0,l1,l2,l3;
        split1(v.x,h0,l0); split1(v.y,h1,l1); split1(v.z,h2,l2); split1(v.w,h3,l3);
        __nv_bfloat162* H = (__nv_bfloat162*)(g_Bh + (size_t)m * HH * HH);
        __nv_bfloat162* L = (__nv_bfloat162*)(g_Bl + (size_t)m * HH * HH);
        H[2*i]   = __nv_bfloat162(h0,h1);
        H[2*i+1] = __nv_bfloat162(h2,h3);
        L[2*i]   = __nv_bfloat162(l0,l1);
        L[2*i+1] = __nv_bfloat162(l2,l3);
    }
}

// ---------------- tensor-core GEMM (bf16x3 split, fp32 accum) --------------
// KC=32, 2-stage cp.async, 2 CTAs/SM.
// smode: 0 = none, 1 = GAT scores (avec[0:H], avec[H:2H] dots -> sp1,sp2),
//        2 = pool scores (tanh(val) dot avec[0:H] -> sp1)
#define KC 32
#define SA_ELEMS (2*128*40)
#define SB_ELEMS (2*32*136)
#define STAGE_ELEMS (SA_ELEMS + SB_ELEMS)   // 18944
#define SA_IDX(st,sp,r,c) ((size_t)(st)*STAGE_ELEMS + ((sp)*128 + (r))*40 + (c))
#define SB_IDX(st,sp,r,c) ((size_t)(st)*STAGE_ELEMS + SA_ELEMS + ((sp)*32 + (r))*136 + (c))
#define SMEM_BYTES (2 * STAGE_ELEMS * 2)    // 75776 B -> 2 CTAs/SM

__global__ __launch_bounds__(256, 2) void gemm_bf16x3(
    const __nv_bfloat16* __restrict__ Ah, const __nv_bfloat16* __restrict__ Al,
    const __nv_bfloat16* __restrict__ Bh, const __nv_bfloat16* __restrict__ Bl,
    const float* __restrict__ bias, int M,
    const float* __restrict__ avec, int smode,
    __nv_bfloat16* __restrict__ Ch, __nv_bfloat16* __restrict__ Cl)
{
    extern __shared__ __nv_bfloat16 sm[];
    const int tid = threadIdx.x;
    const int lane = tid & 31, wid = tid >> 5;
    const int warp_m = wid >> 1, warp_n = wid & 1;
    const int bm = blockIdx.y * 128, bn = blockIdx.x * 128;

    const int ar = tid >> 2, ac = (tid & 3) * 8;
    const int br = tid >> 4, bc = (tid & 15) * 8;
    const int rA0 = min(bm + ar, M - 1);
    const int rA1 = min(bm + ar + 64, M - 1);

    float acc[2][8][4] = {};
    const __nv_bfloat16* As[2] = {Ah, Al};
    const __nv_bfloat16* Bs[2] = {Bh, Bl};

    auto load_stage = [&](int st, int k0) {
        #pragma unroll
        for (int s = 0; s < 2; s++) {
            unsigned d0 = (unsigned)__cvta_generic_to_shared(&sm[SA_IDX(st, s, ar, ac)]);
            CP16(d0, As[s] + (size_t)rA0 * HH + k0 + ac);
            unsigned d1 = (unsigned)__cvta_generic_to_shared(&sm[SA_IDX(st, s, ar + 64, ac)]);
            CP16(d1, As[s] + (size_t)rA1 * HH + k0 + ac);
            unsigned e0 = (unsigned)__cvta_generic_to_shared(&sm[SB_IDX(st, s, br, bc)]);
            CP16(e0, Bs[s] + (size_t)(k0 + br) * HH + bn + bc);
            unsigned e1 = (unsigned)__cvta_generic_to_shared(&sm[SB_IDX(st, s, br + 16, bc)]);
            CP16(e1, Bs[s] + (size_t)(k0 + br + 16) * HH + bn + bc);
        }
        asm volatile("cp.async.commit_group;" ::: "memory");
    };

    load_stage(0, 0);

    const int lrow = lane & 15, lcol = (lane >> 4) * 8;
    const int NCH = HH / KC;   // 24

    for (int c = 0; c < NCH; c++) {
        asm volatile("cp.async.wait_group 0;" ::: "memory");
        __syncthreads();
        if (c + 1 < NCH) load_stage((c + 1) & 1, (c + 1) * KC);
        const int st = c & 1;

        #pragma unroll
        for (int ks = 0; ks < 2; ks++) {
            const int kb = ks * 16;
            unsigned a[2][2][4];
            #pragma unroll
            for (int mt = 0; mt < 2; mt++)
                #pragma unroll
                for (int s = 0; s < 2; s++)
                    ldsm4(a[s][mt], &sm[SA_IDX(st, s, warp_m * 32 + mt * 16 + lrow, kb + lcol)]);
            #pragma unroll
            for (int g = 0; g < 4; g++) {
                unsigned bh[4], bl[4];
                ldsm4t(bh, &sm[SB_IDX(st, 0, kb + lrow, warp_n * 64 + g * 16 + lcol)]);
                ldsm4t(bl, &sm[SB_IDX(st, 1, kb + lrow, warp_n * 64 + g * 16 + lcol)]);
                #pragma unroll
                for (int mt = 0; mt < 2; mt++) {
                    mma16816(acc[mt][2*g],   a[0][mt], bh);
                    mma16816(acc[mt][2*g],   a[0][mt], bl);
                    mma16816(acc[mt][2*g],   a[1][mt], bh);
                    mma16816(acc[mt][2*g+1], a[0][mt], bh + 2);
                    mma16816(acc[mt][2*g+1], a[0][mt], bl + 2);
                    mma16816(acc[mt][2*g+1], a[1][mt], bh + 2);
                }
            }
        }
    }

    // ---- epilogue ----
    const int er = bm + warp_m * 32 + (lane >> 2);
    const int ec = bn + warp_n * 64 + (lane & 3) * 2;
    float p1[2][2] = {}, p2[2][2] = {};
    #pragma unroll
    for (int mt = 0; mt < 2; mt++)
        #pragma unroll
        for (int nt = 0; nt < 8; nt++) {
            int r = er + mt * 16;
            int cc = ec + nt * 8;
            float b0 = bias[cc], b1 = bias[cc + 1];
            float v00 = acc[mt][nt][0] + b0, v01 = acc[mt][nt][1] + b1;
            float v10 = acc[mt][nt][2] + b0, v11 = acc[mt][nt][3] + b1;
            if (Ch) {
                if (r < M) {
                    size_t off = (size_t)r * HH + cc;
                    __nv_bfloat16 h0,l0,h1,l1;
                    split1(v00,h0,l0); split1(v01,h1,l1);
                    *(__nv_bfloat162*)(Ch + off) = __nv_bfloat162(h0,h1);
                    *(__nv_bfloat162*)(Cl + off) = __nv_bfloat162(l0,l1);
                }
                if (r + 8 < M) {
                    size_t off = (size_t)(r + 8) * HH + cc;
                    __nv_bfloat16 h0,l0,h1,l1;
                    split1(v10,h0,l0); split1(v11,h1,l1);
                    *(__nv_bfloat162*)(Ch + off) = __nv_bfloat162(h0,h1);
                    *(__nv_bfloat162*)(Cl + off) = __nv_bfloat162(l0,l1);
                }
            }
            if (smode == 1) {
                float au0 = avec[cc], au1 = avec[cc + 1];
                float av0 = avec[HH + cc], av1 = avec[HH + cc + 1];
                p1[mt][0] += v00 * au0 + v01 * au1;
                p2[mt][0] += v00 * av0 + v01 * av1;
                p1[mt][1] += v10 * au0 + v11 * au1;
                p2[mt][1] += v10 * av0 + v11 * av1;
            } else if (smode == 2) {
                float au0 = avec[cc], au1 = avec[cc + 1];
                p1[mt][0] += tanhf(v00) * au0 + tanhf(v01) * au1;
                p1[mt][1] += tanhf(v10) * au0 + tanhf(v11) * au1;
            }
        }
    if (smode) {
        #pragma unroll
        for (int mt = 0; mt < 2; mt++)
            #pragma unroll
            for (int h = 0; h < 2; h++) {
                #pragma unroll
                for (int o = 1; o <= 2; o <<= 1) {
                    p1[mt][h] += __shfl_xor_sync(~0u, p1[mt][h], o);
                    if (smode == 1) p2[mt][h] += __shfl_xor_sync(~0u, p2[mt][h], o);
                }
            }
        if ((lane & 3) == 0) {
            int slot = blockIdx.x * 2 + warp_n;
            #pragma unroll
            for (int mt = 0; mt < 2; mt++)
                #pragma unroll
                for (int h = 0; h < 2; h++) {
                    int r = er + mt * 16 + h * 8;
                    if (r < M) {
                        g_sp1[(size_t)slot * MTOT + r] = p1[mt][h];
                        if (smode == 1)
                            g_sp2[(size_t)slot * MTOT + r] = p2[mt][h];
                    }
                }
        }
    }
}

// -- 3) GAT tail: reduce partials, masked softmax, bf16x3 mma apply, elu ----
// N=256 per CTA (grid (3,64) = 192 CTAs = single wave at 2 CTAs/SM).
#define AP_ATT_H 0
#define AP_ATT_L 4608
#define AP_WH_H  9216
#define AP_WHSTR 264
#define AP_WH_L  26112
#define AP_FLT   43008
#define AP_SMEM_BYTES (43008*2 + 512)   // 86528 B -> 2 CTAs/SM

__global__ __launch_bounds__(256, 2) void gat_apply_kernel(
    const __nv_bfloat16* __restrict__ Whh, const __nv_bfloat16* __restrict__ Whl,
    const int* __restrict__ adj, const float* __restrict__ ab,
    const __nv_bfloat16* __restrict__ residh, const __nv_bfloat16* __restrict__ residl,
    __nv_bfloat16* __restrict__ hi, __nv_bfloat16* __restrict__ lo)
{
    extern __shared__ __nv_bfloat16 sm2[];
    float* asrc_s = (float*)(sm2 + AP_FLT);
    float* adst_s = asrc_s + 64;
    int b = blockIdx.y, ch = blockIdx.x;   // ch: 256-col chunk (0..2)
    int t = threadIdx.x, lane = t & 31, w = t >> 5;

    {   // async load Wh hi/lo chunk [64 k-rows][256 cols], rows >= NN clamped
        int kr = t >> 2;
        int cg = (t & 3) * 8;
        int grow = b * NN + min(kr, NN - 1);
        const __nv_bfloat16* srch = Whh + (size_t)grow * HH + ch * 256;
        const __nv_bfloat16* srcl = Whl + (size_t)grow * HH + ch * 256;
        #pragma unroll
        for (int p = 0; p < 8; p++) {
            int col = cg + p * 32;
            unsigned dh = (unsigned)__cvta_generic_to_shared(&sm2[AP_WH_H + kr * AP_WHSTR + col]);
            CP16(dh, srch + col);
            unsigned dl = (unsigned)__cvta_generic_to_shared(&sm2[AP_WH_L + kr * AP_WHSTR + col]);
            CP16(dl, srcl + col);
        }
        asm volatile("cp.async.commit_group;\n" ::: "memory");
    }
    {   // zero ATT_H + ATT_L
        unsigned long long* z = (unsigned long long*)sm2;
        for (int i = t; i < 2304; i += 256) z[i] = 0ull;
    }
    if (t < 2 * NN) {   // reduce the 12 score partials
        int i = t % NN;
        const float* sp = (t < NN) ? g_sp1 : g_sp2;
        float s = 0.f;
        #pragma unroll
        for (int c = 0; c < 12; c++) s += sp[(size_t)c * MTOT + b * NN + i];
        ((t < NN) ? asrc_s : adst_s)[i] = s;
    }
    __syncthreads();

    float abv = *ab;
    for (int i = w; i < NN; i += 8) {
        float ai = asrc_s[i];
        const int* adjr = adj + ((size_t)b * NN + i) * NN;
        int j2 = lane + 32;
        float v0 = ai + adst_s[lane] + abv;
        v0 = v0 >= 0.f ? v0 : 0.3f * v0;
        float e0 = (adjr[lane] > 0) ? v0 : -1e30f;
        float e1 = -1e30f;
        if (j2 < NN) {
            float v1 = ai + adst_s[j2] + abv;
            v1 = v1 >= 0.f ? v1 : 0.3f * v1;
            e1 = (adjr[j2] > 0) ? v1 : -1e30f;
        }
        float m = fmaxf(e0, e1);
        #pragma unroll
        for (int o = 16; o; o >>= 1) m = fmaxf(m, __shfl_xor_sync(~0u, m, o));
        float x0 = expf(e0 - m);
        float x1 = (j2 < NN) ? expf(e1 - m) : 0.f;
        float s = x0 + x1;
        #pragma unroll
        for (int o = 16; o; o >>= 1) s += __shfl_xor_sync(~0u, s, o);
        float inv = 1.f / s;
        split1(x0 * inv, sm2[AP_ATT_H + i * 72 + lane], sm2[AP_ATT_L + i * 72 + lane]);
        if (j2 < NN)
            split1(x1 * inv, sm2[AP_ATT_H + i * 72 + j2], sm2[AP_ATT_L + i * 72 + j2]);
    }
    asm volatile("cp.async.wait_group 0;\n" ::: "memory");
    __syncthreads();

    // mma: [64x64] att (hi/lo) @ [64 x 32-per-warp] Wh (hi/lo), bf16x3
    const int lrow = lane & 15, lcol = (lane >> 4) * 8;
    const int n0 = w * 32;
    float acc[4][4][4] = {};
    #pragma unroll
    for (int kb = 0; kb < 64; kb += 16) {
        unsigned ah[4][4], al[4][4];
        #pragma unroll
        for (int mt = 0; mt < 4; mt++) {
            ldsm4(ah[mt], &sm2[AP_ATT_H + (mt * 16 + lrow) * 72 + kb + lcol]);
            ldsm4(al[mt], &sm2[AP_ATT_L + (mt * 16 + lrow) * 72 + kb + lcol]);
        }
        #pragma unroll
        for (int g = 0; g < 2; g++) {
            unsigned bh[4], bl[4];
            ldsm4t(bh, &sm2[AP_WH_H + (kb + lrow) * AP_WHSTR + n0 + g * 16 + lcol]);
            ldsm4t(bl, &sm2[AP_WH_L + (kb + lrow) * AP_WHSTR + n0 + g * 16 + lcol]);
            #pragma unroll
            for (int mt = 0; mt < 4; mt++) {
                mma16816(acc[mt][2*g],   ah[mt], bh);
                mma16816(acc[mt][2*g],   ah[mt], bl);
                mma16816(acc[mt][2*g],   al[mt], bh);
                mma16816(acc[mt][2*g+1], ah[mt], bh + 2);
                mma16816(acc[mt][2*g+1], ah[mt], bl + 2);
                mma16816(acc[mt][2*g+1], al[mt], bh + 2);
            }
        }
    }
    #pragma unroll
    for (int mt = 0; mt < 4; mt++)
        #pragma unroll
        for (int nt = 0; nt < 4; nt++) {
            int cc = ch * 256 + n0 + nt * 8 + (lane & 3) * 2;
            #pragma unroll
            for (int h = 0; h < 2; h++) {
                int row = mt * 16 + (lane >> 2) + h * 8;
                if (row < NN) {
                    float vx = acc[mt][nt][2*h], vy = acc[mt][nt][2*h + 1];
                    vx = vx > 0.f ? vx : expm1f(vx);
                    vy = vy > 0.f ? vy : expm1f(vy);
                    size_t off = ((size_t)b * NN + row) * HH + cc;
                    if (residh) {
                        __nv_bfloat162 rh = *(const __nv_bfloat162*)(residh + off);
                        __nv_bfloat162 rl = *(const __nv_bfloat162*)(residl + off);
                        vx += __bfloat162float(rh.x) + __bfloat162float(rl.x);
                        vy += __bfloat162float(rh.y) + __bfloat162float(rl.y);
                    }
                    __nv_bfloat16 h0,l0,h1,l1;
                    split1(vx,h0,l0); split1(vy,h1,l1);
                    *(__nv_bfloat162*)(hi + off) = __nv_bfloat162(h0,h1);
                    *(__nv_bfloat162*)(lo + off) = __nv_bfloat162(l0,l1);
                }
            }
        }
}

// -------- 5) pooling: reduce tanh-dot partials, softmax, weighted sum ------
__global__ __launch_bounds__(256) void pool_kernel(
    const __nv_bfloat16* __restrict__ Hh, const __nv_bfloat16* __restrict__ Hl,
    float* __restrict__ D)
{
    int b = blockIdx.x;
    int t = threadIdx.x;
    __shared__ float sc[NN];
    if (t < NN) {
        float s = 0.f;
        #pragma unroll
        for (int c = 0; c < 12; c++) s += g_sp1[(size_t)c * MTOT + b * NN + t];
        sc[t] = s;
    }
    __syncthreads();
    if (t == 0) {
        float m = -1e30f;
        for (int n = 0; n < NN; n++) m = fmaxf(m, sc[n]);
        float s = 0.f;
        for (int n = 0; n < NN; n++) { sc[n] = expf(sc[n] - m); s += sc[n]; }
        float inv = 1.f / s;
        for (int n = 0; n < NN; n++) sc[n] *= inv;
    }
    __syncthreads();
    for (int h2 = t; h2 < HH / 2; h2 += 256) {
        float ax = 0.f, ay = 0.f;
        #pragma unroll 5
        for (int n = 0; n < NN; n++) {
            size_t off = ((size_t)b * NN + n) * HH + h2 * 2;
            __nv_bfloat162 vh = *(const __nv_bfloat162*)(Hh + off);
            __nv_bfloat162 vl = *(const __nv_bfloat162*)(Hl + off);
            float s = sc[n];
            ax = fmaf(s, __bfloat162float(vh.x) + __bfloat162float(vl.x), ax);
            ay = fmaf(s, __bfloat162float(vh.y) + __bfloat162float(vl.y), ay);
        }
        D[(size_t)b * HH + h2 * 2]     = ax;
        D[(size_t)b * HH + h2 * 2 + 1] = ay;
    }
}

// -------- 6) final linear: out[64,768] = D @ Wl + bl (fp32, wide grid) -----
__global__ __launch_bounds__(128) void final_linear_kernel(
    const float* __restrict__ D, const float* __restrict__ W,
    const float* __restrict__ bias, float* __restrict__ out)
{
    int b = blockIdx.y;
    int o = blockIdx.x * 128 + threadIdx.x;
    __shared__ float Ds[HH];
    for (int i = threadIdx.x; i < HH; i += 128)
        Ds[i] = D[(size_t)b * HH + i];
    __syncthreads();
    float acc = 0.f;
    #pragma unroll 8
    for (int h = 0; h < HH; h++)
        acc = fmaf(Ds[h], W[(size_t)h * OO + o], acc);
    out[(size_t)b * OO + o] = acc + bias[o];
}

// ---------------- launch ----------------------------------------------------
extern "C" void kernel_launch(void* const* d_in, const int* in_sizes, int n_in,
                              void* d_out, int out_size)
{
    const float* emb = (const float*)d_in[0];
    const int*   ids = (const int*)  d_in[1];
    const int*   adj = (const int*)  d_in[2];
    const float* W1  = (const float*)d_in[3];
    const float* b1  = (const float*)d_in[4];
    const float* a1  = (const float*)d_in[5];
    const float* ab1 = (const float*)d_in[6];
    const float* W2  = (const float*)d_in[7];
    const float* b2  = (const float*)d_in[8];
    const float* a2  = (const float*)d_in[9];
    const float* ab2 = (const float*)d_in[10];
    const float* Wa  = (const float*)d_in[11];
    const float* ba  = (const float*)d_in[12];
    const float* v   = (const float*)d_in[13];
    const float* Wl  = (const float*)d_in[14];
    const float* bl  = (const float*)d_in[15];
    float* out = (float*)d_out;

    void *pD, *pXh, *pXl, *pAh, *pAl, *pWhh, *pWhl, *pBh, *pBl;
    cudaGetSymbolAddress(&pD, g_D);
    cudaGetSymbolAddress(&pXh, g_Xh);
    cudaGetSymbolAddress(&pXl, g_Xl);
    cudaGetSymbolAddress(&pAh, g_Ah);
    cudaGetSymbolAddress(&pAl, g_Al);
    cudaGetSymbolAddress(&pWhh, g_Whh);
    cudaGetSymbolAddress(&pWhl, g_Whl);
    cudaGetSymbolAddress(&pBh, g_Bh);
    cudaGetSymbolAddress(&pBl, g_Bl);
    float* D    = (float*)pD;
    __nv_bfloat16* Xh  = (__nv_bfloat16*)pXh;
    __nv_bfloat16* Xl  = (__nv_bfloat16*)pXl;
    __nv_bfloat16* Ah  = (__nv_bfloat16*)pAh;
    __nv_bfloat16* Al  = (__nv_bfloat16*)pAl;
    __nv_bfloat16* Whh = (__nv_bfloat16*)pWhh;
    __nv_bfloat16* Whl = (__nv_bfloat16*)pWhl;
    __nv_bfloat16* Bh  = (__nv_bfloat16*)pBh;
    __nv_bfloat16* Bl  = (__nv_bfloat16*)pBl;
    const size_t WSZ = (size_t)HH * HH;

    cudaFuncSetAttribute(gemm_bf16x3,
                         cudaFuncAttributeMaxDynamicSharedMemorySize, SMEM_BYTES);
    cudaFuncSetAttribute(gat_apply_kernel,
                         cudaFuncAttributeMaxDynamicSharedMemorySize, AP_SMEM_BYTES);

    dim3 ggemm(HH / 128, MTOT / 128);   // (6, 25)
    dim3 gapply(HH / 256, BB);          // (3, 64) = 192 CTAs (single wave)
    dim3 gfinal(OO / 128, BB);          // (6, 64)

    // 0+1) fused prep: gather+PE and weight splits in one launch
    prep_kernel<<<MTOT + 3 * SPLITW_BLOCKS, 256>>>(emb, ids, W1, W2, Wa);
    // 2) Wh1 = X @ W1 + b1 -> bf16 splits (+ a1 score partials, mode 1)
    gemm_bf16x3<<<ggemm, 256, SMEM_BYTES>>>(Xh, Xl, Bh, Bl, b1, MTOT, a1, 1, Whh, Whl);
    // 3) GAT layer 1 tail (softmax + tensor-core apply, N=256) -> split(H1)
    gat_apply_kernel<<<gapply, 256, AP_SMEM_BYTES>>>(Whh, Whl, adj, ab1,
                                                     nullptr, nullptr, Ah, Al);
    // 4) Wh2 = H1 @ W2 + b2 -> bf16 splits (+ a2 score partials, mode 1)
    gemm_bf16x3<<<ggemm, 256, SMEM_BYTES>>>(Ah, Al, Bh + WSZ, Bl + WSZ, b2, MTOT, a2, 1, Whh, Whl);
    // 5) GAT layer 2 tail (+ residual from X split) -> Hres splits only
    gat_apply_kernel<<<gapply, 256, AP_SMEM_BYTES>>>(Whh, Whl, adj, ab2,
                                                     Xh, Xl, Ah, Al);
    // 6) pooling-score GEMM: tanh(Hres@Wa+ba) dot v -> partials only (mode 2)
    gemm_bf16x3<<<ggemm, 256, SMEM_BYTES>>>(Ah, Al, Bh + 2*WSZ, Bl + 2*WSZ, ba, MTOT, v, 2, nullptr, nullptr);
    // 7) pooling: reduce partials + softmax + weighted sum of Hres splits
    pool_kernel<<<BB, 256>>>(Ah, Al, D);
    // 8) out = D @ Wl + bl (wide grid)
    final_linear_kernel<<<gfinal, 128>>>(D, Wl, bl, out);
}